// round 13
// baseline (speedup 1.0000x reference)
#include <cuda_runtime.h>
#include <cuda_bf16.h>
#include <cstdint>
#include <math.h>

typedef __nv_bfloat16 bf16;

#define Bb   4
#define Ss   512
#define Ee   512
#define Hh   8
#define DHd  64
#define HIDh 128
#define MTOT 2048
#define SZQ  (2048 * 512)
#define SCsz ((size_t)Bb * Hh * Ss * Ss)
#define LUTN 2048

// ---- scratch (allocation-free: __device__ globals) ----
__device__ bf16  g_xhi[MTOT * Ee], g_xlo[MTOT * Ee];
__device__ bf16  g_whi[3 * Ee * Ee], g_wlo[3 * Ee * Ee];
__device__ bf16  g_wohi[Ee * Ee], g_wolo[Ee * Ee];
__device__ float g_biasqkv[3 * Ee];
__device__ bf16  g_qhi[3 * SZQ], g_qlo[3 * SZQ];   // q|k|v splits
__device__ float g_scores[SCsz];
__device__ float g_mean2[2][(size_t)Bb * Ss * Ss];  // per-half clipped head sums
__device__ bf16  g_phi[SCsz], g_plo[SCsz];
__device__ float g_tpre[(size_t)Bb * Ss * Ss];
__device__ bf16  g_chi[MTOT * Ee], g_clo[MTOT * Ee];
__device__ float g_partial[Bb * Ss * 4];
__device__ float g_Acoef[Bb];
__device__ float g_Ccoef[Bb];
__device__ float2 g_lut2[LUTN];     // {sig(i), sig(i+1)-sig(i)}
__device__ int   g_cnt[Bb];         // zero-init; self-resetting per launch

// =====================================================================
// low-level helpers
// =====================================================================
__device__ __forceinline__ uint32_t smem_u32(const void* p) {
    uint32_t a;
    asm("{ .reg .u64 t; cvta.to.shared.u64 t, %1; cvt.u32.u64 %0, t; }" : "=r"(a) : "l"(p));
    return a;
}
__device__ __forceinline__ void cp16(uint32_t dst, const void* src) {
    asm volatile("cp.async.cg.shared.global [%0], [%1], 16;" :: "r"(dst), "l"(src));
}
__device__ __forceinline__ void cp_commit() {
    asm volatile("cp.async.commit_group;" ::: "memory");
}
__device__ __forceinline__ void ldsm4(uint32_t addr, uint32_t& r0, uint32_t& r1,
                                      uint32_t& r2, uint32_t& r3) {
    asm volatile("ldmatrix.sync.aligned.m8n8.x4.shared.b16 {%0,%1,%2,%3}, [%4];"
                 : "=r"(r0), "=r"(r1), "=r"(r2), "=r"(r3) : "r"(addr));
}
__device__ __forceinline__ void ldsm4t(uint32_t addr, uint32_t& r0, uint32_t& r1,
                                       uint32_t& r2, uint32_t& r3) {
    asm volatile("ldmatrix.sync.aligned.m8n8.x4.trans.shared.b16 {%0,%1,%2,%3}, [%4];"
                 : "=r"(r0), "=r"(r1), "=r"(r2), "=r"(r3) : "r"(addr));
}
__device__ __forceinline__ void mma16816(float* d, const uint32_t* a, uint32_t b0, uint32_t b1) {
    asm volatile("mma.sync.aligned.m16n8k16.row.col.f32.bf16.bf16.f32 "
                 "{%0,%1,%2,%3}, {%4,%5,%6,%7}, {%8,%9}, {%0,%1,%2,%3};"
                 : "+f"(d[0]), "+f"(d[1]), "+f"(d[2]), "+f"(d[3])
                 : "r"(a[0]), "r"(a[1]), "r"(a[2]), "r"(a[3]), "r"(b0), "r"(b1));
}

// swizzled smem offset: 128B rows, 16B chunks, c8 ^= (r & 7)
#define SWZ(r, c8) ((((uint32_t)(r)) << 7) + ((((uint32_t)(c8)) ^ ((uint32_t)(r) & 7)) << 4))

__device__ __forceinline__ void load_tile128(uint32_t dst, const bf16* __restrict__ src,
                                             int tid) {
#pragma unroll
    for (int i = 0; i < 4; i++) {
        int ch = tid + i * 256;
        int r = ch >> 3, c8 = ch & 7;
        cp16(dst + SWZ(r, c8), src + (size_t)r * 512 + c8 * 8);
    }
}
__device__ __forceinline__ void load_tile64(uint32_t dst, const bf16* __restrict__ src,
                                            int tid) {
#pragma unroll
    for (int i = 0; i < 2; i++) {
        int ch = tid + i * 256;
        int r = ch >> 3, c8 = ch & 7;
        cp16(dst + SWZ(r, c8), src + (size_t)r * 512 + c8 * 8);
    }
}

// warp compute over one 64-K slab: warp tile 32(m) x 64(n), acc[2][8][4]
__device__ __forceinline__ void mma_slab_n64(uint32_t As, uint32_t Bs,
                                             int warp_m0, int warp_n0, int lane,
                                             float acc[2][8][4]) {
#pragma unroll
    for (int kk = 0; kk < 4; kk++) {
        uint32_t a[2][4];
#pragma unroll
        for (int mi = 0; mi < 2; mi++) {
            int r = warp_m0 + mi * 16 + (lane & 15);
            uint32_t addr = As + (r << 7) + ((((kk << 1) + (lane >> 4)) ^ (r & 7)) << 4);
            ldsm4(addr, a[mi][0], a[mi][1], a[mi][2], a[mi][3]);
        }
#pragma unroll
        for (int pr = 0; pr < 4; pr++) {
            int nr = warp_n0 + pr * 16 + (lane & 7) + ((lane >> 4) << 3);
            uint32_t addr = Bs + (nr << 7) + ((((kk << 1) + ((lane >> 3) & 1)) ^ (nr & 7)) << 4);
            uint32_t b0, b1, b2, b3;
            ldsm4(addr, b0, b1, b2, b3);
#pragma unroll
            for (int mi = 0; mi < 2; mi++) {
                mma16816(acc[mi][2 * pr + 0], a[mi], b0, b1);
                mma16816(acc[mi][2 * pr + 1], a[mi], b2, b3);
            }
        }
    }
}

// warp tile 16(m) x 32(n), B n-major (NT), acc[4][4]
__device__ __forceinline__ void mma_slab_m16n32_nt(uint32_t As, uint32_t Bs,
                                                   int warp_m0, int warp_n0, int lane,
                                                   float acc[4][4]) {
#pragma unroll
    for (int kk = 0; kk < 4; kk++) {
        uint32_t a[4];
        {
            int r = warp_m0 + (lane & 15);
            uint32_t addr = As + (r << 7) + ((((kk << 1) + (lane >> 4)) ^ (r & 7)) << 4);
            ldsm4(addr, a[0], a[1], a[2], a[3]);
        }
#pragma unroll
        for (int pr = 0; pr < 2; pr++) {
            int nr = warp_n0 + pr * 16 + (lane & 7) + ((lane >> 4) << 3);
            uint32_t addr = Bs + (nr << 7) + ((((kk << 1) + ((lane >> 3) & 1)) ^ (nr & 7)) << 4);
            uint32_t b0, b1, b2, b3;
            ldsm4(addr, b0, b1, b2, b3);
            mma16816(acc[2 * pr + 0], a, b0, b1);
            mma16816(acc[2 * pr + 1], a, b2, b3);
        }
    }
}

// warp tile 16(m) x 32(n), B k-major (trans), acc[4][4]
__device__ __forceinline__ void mma_slab_m16n32_t(uint32_t As, uint32_t Bs,
                                                  int warp_m0, int warp_n0, int lane,
                                                  float acc[4][4]) {
#pragma unroll
    for (int kk = 0; kk < 4; kk++) {
        uint32_t a[4];
        {
            int r = warp_m0 + (lane & 15);
            uint32_t addr = As + (r << 7) + ((((kk << 1) + (lane >> 4)) ^ (r & 7)) << 4);
            ldsm4(addr, a[0], a[1], a[2], a[3]);
        }
#pragma unroll
        for (int pr = 0; pr < 2; pr++) {
            int kr = kk * 16 + (lane & 15);
            int c8 = ((warp_n0 + pr * 16) >> 3) + (lane >> 4);
            uint32_t addr = Bs + (kr << 7) + ((c8 ^ (kr & 7)) << 4);
            uint32_t b0, b1, b2, b3;
            ldsm4t(addr, b0, b1, b2, b3);
            mma16816(acc[2 * pr + 0], a, b0, b1);
            mma16816(acc[2 * pr + 1], a, b2, b3);
        }
    }
}

#define STG_BIG   32768
#define SMEM_BIG  (3 * STG_BIG)
#define STG_SM    16384
#define SMEM_SM   (3 * STG_SM)

// =====================================================================
// big NT GEMM (MODE 0 qkv split-out / MODE 1 oproj fp32 out)
// =====================================================================
template <int MODE>
__global__ __launch_bounds__(256) void gemm_big(
    const bf16* __restrict__ Ahi, const bf16* __restrict__ Alo,
    const bf16* __restrict__ Bhi, const bf16* __restrict__ Blo,
    const float* __restrict__ bias, float* __restrict__ outf,
    bf16* __restrict__ ohi, bf16* __restrict__ olo)
{
    extern __shared__ char dsm[];
    const uint32_t sb = smem_u32(dsm);
    const int tid = threadIdx.x;
    const int lane = tid & 31, w = tid >> 5;
    const int warp_m0 = (w >> 1) * 32, warp_n0 = (w & 1) * 64;
    const int bn = blockIdx.x * 128, bm = blockIdx.y * 128;
    const int NS = 24;

    float acc[2][8][4];
#pragma unroll
    for (int mi = 0; mi < 2; mi++)
#pragma unroll
        for (int nf = 0; nf < 8; nf++)
#pragma unroll
            for (int q = 0; q < 4; q++) acc[mi][nf][q] = 0.f;

#define LOAD_SLAB(s, st)                                                        \
    do {                                                                        \
        int part = (s) >> 3;                                                    \
        int k0 = ((s) & 7) * 64;                                                \
        const bf16* Asrc = ((part == 2) ? Alo : Ahi) + (size_t)bm * 512 + k0;   \
        const bf16* Bsrc = ((part == 1) ? Blo : Bhi) + (size_t)bn * 512 + k0;   \
        load_tile128(sb + (st) * STG_BIG, Asrc, tid);                           \
        load_tile128(sb + (st) * STG_BIG + 16384, Bsrc, tid);                   \
        cp_commit();                                                            \
    } while (0)

    LOAD_SLAB(0, 0);
    LOAD_SLAB(1, 1);
#pragma unroll 1
    for (int s = 0; s < NS; s++) {
        if (s + 2 < NS) {
            LOAD_SLAB(s + 2, (s + 2) % 3);
            asm volatile("cp.async.wait_group 2;" ::: "memory");
        } else if (s + 1 < NS) {
            asm volatile("cp.async.wait_group 1;" ::: "memory");
        } else {
            asm volatile("cp.async.wait_group 0;" ::: "memory");
        }
        __syncthreads();
        uint32_t st = sb + (s % 3) * STG_BIG;
        mma_slab_n64(st, st + 16384, warp_m0, warp_n0, lane, acc);
        __syncthreads();
    }
#undef LOAD_SLAB

    const int mrow = lane >> 2, ncol = 2 * (lane & 3);
#pragma unroll
    for (int mi = 0; mi < 2; mi++) {
#pragma unroll
        for (int nf = 0; nf < 8; nf++) {
            int n_g = bn + warp_n0 + nf * 8 + ncol;
            float2 bb = *(const float2*)(bias + n_g);
#pragma unroll
            for (int hh = 0; hh < 2; hh++) {
                int m = bm + warp_m0 + mi * 16 + mrow + hh * 8;
                float v0 = acc[mi][nf][hh * 2 + 0] + bb.x;
                float v1 = acc[mi][nf][hh * 2 + 1] + bb.y;
                if (MODE == 0) {
                    int seg = n_g >> 9, col = n_g & 511;
                    bf16 h0 = __float2bfloat16(v0), h1 = __float2bfloat16(v1);
                    __nv_bfloat162 hv; hv.x = h0; hv.y = h1;
                    __nv_bfloat162 lv;
                    lv.x = __float2bfloat16(v0 - __bfloat162float(h0));
                    lv.y = __float2bfloat16(v1 - __bfloat162float(h1));
                    *(__nv_bfloat162*)(ohi + (size_t)seg * SZQ + (size_t)m * 512 + col) = hv;
                    *(__nv_bfloat162*)(olo + (size_t)seg * SZQ + (size_t)m * 512 + col) = lv;
                } else {
                    float2 o; o.x = v0; o.y = v1;
                    *(float2*)(outf + (size_t)m * 512 + n_g) = o;
                }
            }
        }
    }
}

// =====================================================================
// scores: each CTA covers 4 heads of one 64x64 tile (half = z&1).
// 12-slab continuous pipeline; writes 4 score planes + partial mean sum.
// grid (8, 8, Bb*2) = 512 CTAs
// =====================================================================
__global__ __launch_bounds__(256) void gemm_scores_mma()
{
    extern __shared__ char dsm[];
    const uint32_t sb = smem_u32(dsm);
    const int tid = threadIdx.x;
    const int lane = tid & 31, w = tid >> 5;
    const int warp_m0 = (w >> 1) * 16, warp_n0 = (w & 1) * 32;
    int b = blockIdx.z >> 1;
    int half = blockIdx.z & 1;
    int hb = half * 4;
    int bn = blockIdx.x * 64, bm = blockIdx.y * 64;
    const int NS = 12;  // 4 heads x 3 split-parts

    float macc[4][4];
#pragma unroll
    for (int nf = 0; nf < 4; nf++)
#pragma unroll
        for (int q = 0; q < 4; q++) macc[nf][q] = 0.f;

#define LOAD_SLAB(g, st)                                                                      \
    do {                                                                                      \
        int h_ = hb + (g) / 3, s_ = (g) % 3;                                                  \
        const bf16* Asrc = (s_ == 2 ? g_qlo : g_qhi) + (size_t)(b * 512 + bm) * 512 + h_ * 64; \
        const bf16* Bsrc = (s_ == 1 ? g_qlo : g_qhi) + SZQ + (size_t)(b * 512 + bn) * 512 + h_ * 64; \
        load_tile64(sb + (st) * STG_SM, Asrc, tid);                                           \
        load_tile64(sb + (st) * STG_SM + 8192, Bsrc, tid);                                    \
        cp_commit();                                                                          \
    } while (0)

    LOAD_SLAB(0, 0);
    LOAD_SLAB(1, 1);

    const int mrow = lane >> 2, ncol = 2 * (lane & 3);
#pragma unroll 1
    for (int h2 = 0; h2 < 4; h2++) {
        float acc[4][4];
#pragma unroll
        for (int nf = 0; nf < 4; nf++)
#pragma unroll
            for (int q = 0; q < 4; q++) acc[nf][q] = 0.f;
#pragma unroll
        for (int s = 0; s < 3; s++) {
            int g = h2 * 3 + s;
            if (g + 2 < NS) {
                LOAD_SLAB(g + 2, (g + 2) % 3);
                asm volatile("cp.async.wait_group 2;" ::: "memory");
            } else if (g + 1 < NS) {
                asm volatile("cp.async.wait_group 1;" ::: "memory");
            } else {
                asm volatile("cp.async.wait_group 0;" ::: "memory");
            }
            __syncthreads();
            uint32_t st = sb + (g % 3) * STG_SM;
            mma_slab_m16n32_nt(st, st + 8192, warp_m0, warp_n0, lane, acc);
            __syncthreads();
        }
        // epilogue for head hb+h2: raw store + clipped sum accumulate
        float* Cp = g_scores + ((size_t)(b * Hh + hb + h2)) * Ss * Ss;
#pragma unroll
        for (int nf = 0; nf < 4; nf++) {
            int n_g = bn + warp_n0 + nf * 8 + ncol;
#pragma unroll
            for (int hh = 0; hh < 2; hh++) {
                int m = bm + warp_m0 + mrow + hh * 8;
                float v0 = acc[nf][hh * 2 + 0];
                float v1 = acc[nf][hh * 2 + 1];
                float2 o; o.x = v0; o.y = v1;
                *(float2*)(Cp + (size_t)m * 512 + n_g) = o;
                macc[nf][hh * 2 + 0] += fminf(fmaxf(v0, -15.f), 15.f);
                macc[nf][hh * 2 + 1] += fminf(fmaxf(v1, -15.f), 15.f);
            }
        }
    }
#undef LOAD_SLAB

    // write partial mean plane (raw clipped sum of 4 heads)
    float* Mp = g_mean2[half] + (size_t)b * Ss * Ss;
#pragma unroll
    for (int nf = 0; nf < 4; nf++) {
        int n_g = bn + warp_n0 + nf * 8 + ncol;
#pragma unroll
        for (int hh = 0; hh < 2; hh++) {
            int m = bm + warp_m0 + mrow + hh * 8;
            float2 o;
            o.x = macc[nf][hh * 2 + 0];
            o.y = macc[nf][hh * 2 + 1];
            *(float2*)(Mp + (size_t)m * 512 + n_g) = o;
        }
    }
}

// =====================================================================
// attn*V: per (b,h) ctx = P V; CTA tile 64(m)x64(n), warp 16x32
// =====================================================================
__global__ __launch_bounds__(256) void gemm_attnv_mma()
{
    extern __shared__ char dsm[];
    const uint32_t sb = smem_u32(dsm);
    const int tid = threadIdx.x;
    const int lane = tid & 31, w = tid >> 5;
    const int warp_m0 = (w >> 1) * 16, warp_n0 = (w & 1) * 32;
    int bh = blockIdx.y;
    int b = bh >> 3, h = bh & 7;
    int bm = blockIdx.x * 64;
    const size_t pbase = (size_t)bh * Ss * Ss;
    const int NS = 24;

    float acc[4][4];
#pragma unroll
    for (int nf = 0; nf < 4; nf++)
#pragma unroll
        for (int q = 0; q < 4; q++) acc[nf][q] = 0.f;

#define LOAD_SLAB(s, st)                                                                     \
    do {                                                                                     \
        int part = (s) >> 3;                                                                 \
        int k0 = ((s) & 7) * 64;                                                             \
        const bf16* Asrc = ((part == 2) ? g_plo : g_phi) + pbase + (size_t)bm * 512 + k0;    \
        const bf16* Bsrc = ((part == 1) ? g_qlo : g_qhi) + 2 * (size_t)SZQ                   \
                           + (size_t)(b * 512 + k0) * 512 + h * 64;                          \
        load_tile64(sb + (st) * STG_SM, Asrc, tid);                                          \
        load_tile64(sb + (st) * STG_SM + 8192, Bsrc, tid);                                   \
        cp_commit();                                                                         \
    } while (0)

    LOAD_SLAB(0, 0);
    LOAD_SLAB(1, 1);
#pragma unroll 1
    for (int s = 0; s < NS; s++) {
        if (s + 2 < NS) {
            LOAD_SLAB(s + 2, (s + 2) % 3);
            asm volatile("cp.async.wait_group 2;" ::: "memory");
        } else if (s + 1 < NS) {
            asm volatile("cp.async.wait_group 1;" ::: "memory");
        } else {
            asm volatile("cp.async.wait_group 0;" ::: "memory");
        }
        __syncthreads();
        uint32_t st = sb + (s % 3) * STG_SM;
        mma_slab_m16n32_t(st, st + 8192, warp_m0, warp_n0, lane, acc);
        __syncthreads();
    }
#undef LOAD_SLAB

    const int mrow = lane >> 2, ncol = 2 * (lane & 3);
#pragma unroll
    for (int nf = 0; nf < 4; nf++) {
        int n_g = h * 64 + warp_n0 + nf * 8 + ncol;
#pragma unroll
        for (int hh = 0; hh < 2; hh++) {
            int m = b * 512 + bm + warp_m0 + mrow + hh * 8;
            float v0 = acc[nf][hh * 2 + 0];
            float v1 = acc[nf][hh * 2 + 1];
            bf16 h0 = __float2bfloat16(v0), h1 = __float2bfloat16(v1);
            __nv_bfloat162 hv; hv.x = h0; hv.y = h1;
            __nv_bfloat162 lv;
            lv.x = __float2bfloat16(v0 - __bfloat162float(h0));
            lv.y = __float2bfloat16(v1 - __bfloat162float(h1));
            *(__nv_bfloat162*)(g_chi + (size_t)m * 512 + n_g) = hv;
            *(__nv_bfloat162*)(g_clo + (size_t)m * 512 + n_g) = lv;
        }
    }
}

// =====================================================================
// reductions
// =====================================================================
__device__ __forceinline__ float warp_sum(float v) {
#pragma unroll
    for (int o = 16; o; o >>= 1) v += __shfl_xor_sync(0xffffffffu, v, o);
    return v;
}
template <int NV, int NW>
__device__ __forceinline__ void block_sumN(float* v, float* red) {
    int lane = threadIdx.x & 31, w = threadIdx.x >> 5;
#pragma unroll
    for (int i = 0; i < NV; i++) v[i] = warp_sum(v[i]);
    if (lane == 0)
#pragma unroll
        for (int i = 0; i < NV; i++) red[w * NV + i] = v[i];
    __syncthreads();
    if (w == 0) {
#pragma unroll
        for (int i = 0; i < NV; i++) {
            float x = (lane < NW) ? red[lane * NV + i] : 0.f;
            x = warp_sum(x);
            if (lane == 0) red[i] = x;
        }
    }
    __syncthreads();
#pragma unroll
    for (int i = 0; i < NV; i++) v[i] = red[i];
    __syncthreads();
}

// =====================================================================
// exact sig(mv) evaluator (used only by LUT build)
// =====================================================================
__device__ __forceinline__ float sig_exact(float mv, const float* __restrict__ w1,
                                           const float* __restrict__ b1,
                                           const float* __restrict__ w2, float b2v)
{
    float scaled = mv * 0.05f;
    float av = 0.f;
#pragma unroll 8
    for (int hh = 0; hh < HIDh; hh++) {
        float hv = fmaf(scaled, w1[hh], b1[hh]);
        hv = fminf(fmaxf(hv, 0.f), 5.f);
        av = fmaf(hv, w2[hh], av);
    }
    av += b2v;
    av = fminf(fmaxf(av, -5.f), 5.f);
    float taylor = fminf(fmaxf(fmaf(av, 2.5f, 1.f), 0.5f), 1.5f);
    return 1.f / (1.f + __expf(-taylor));
}

// =====================================================================
// single fused conversion kernel (x, wq, wk, wv, wo, bias, LUT)
// =====================================================================
__global__ __launch_bounds__(256) void conv_all(
    const float* __restrict__ x,
    const float* __restrict__ wq, const float* __restrict__ wk,
    const float* __restrict__ wv, const float* __restrict__ wo,
    const float* __restrict__ bq, const float* __restrict__ bk,
    const float* __restrict__ bv,
    const float* __restrict__ w1, const float* __restrict__ b1,
    const float* __restrict__ w2, const float* __restrict__ b2p)
{
    int bid = blockIdx.x;
    int tid = threadIdx.x;
    const float* src; bf16 *hi, *lo; float scale; int i;
    if (bid < 4096) {
        i = bid * 256 + tid;
        src = x; hi = g_xhi; lo = g_xlo; scale = 1.f;
    } else if (bid < 5120) {
        i = (bid - 4096) * 256 + tid;
        src = wq; hi = g_whi; lo = g_wlo; scale = 0.125f;
    } else if (bid < 6144) {
        i = (bid - 5120) * 256 + tid;
        src = wk; hi = g_whi + Ee * Ee; lo = g_wlo + Ee * Ee; scale = 1.f;
    } else if (bid < 7168) {
        i = (bid - 6144) * 256 + tid;
        src = wv; hi = g_whi + 2 * Ee * Ee; lo = g_wlo + 2 * Ee * Ee; scale = 1.f;
    } else if (bid < 8192) {
        i = (bid - 7168) * 256 + tid;
        src = wo; hi = g_wohi; lo = g_wolo; scale = 1.f;
    } else if (bid < 8199) {
        int j = (bid - 8192) * 256 + tid;
        if (j < 1536) {
            float v = (j < 512) ? bq[j] * 0.125f : (j < 1024 ? bk[j - 512] : bv[j - 1024]);
            g_biasqkv[j] = v;
        }
        return;
    } else {
        int j = (bid - 8199) * 256 + tid;
        if (j < LUTN) {
            float b2v = b2p[0];
            float step = 16.f / (float)LUTN;
            float m0 = -8.f + step * (float)j;
            float s0 = sig_exact(m0, w1, b1, w2, b2v);
            float s1 = sig_exact(m0 + step, w1, b1, w2, b2v);
            float2 e; e.x = s0; e.y = s1 - s0;
            g_lut2[j] = e;
        }
        return;
    }
    float a = src[i] * scale;
    bf16 h = __float2bfloat16(a);
    hi[i] = h;
    lo[i] = __float2bfloat16(a - __bfloat162float(h));
}

// =====================================================================
// transform: 128 threads x float4; reads 2 partial mean planes;
// per-batch scalars computed by the LAST block (fence+counter pattern).
// grid Bb*Ss, block 128
// =====================================================================
__global__ __launch_bounds__(128) void transform_kernel()
{
    __shared__ float red[16];
    __shared__ int isLast;
    int row = blockIdx.x;
    int bb = row >> 9;
    int j4 = threadIdx.x * 4;

    float4 p0 = *(const float4*)(g_mean2[0] + (size_t)row * Ss + j4);
    float4 p1 = *(const float4*)(g_mean2[1] + (size_t)row * Ss + j4);
    float mv[4] = {(p0.x + p1.x) * 0.125f, (p0.y + p1.y) * 0.125f,
                   (p0.z + p1.z) * 0.125f, (p0.w + p1.w) * 0.125f};

    float sig[4], e1[4];
    float s_e1 = 0.f, s_m = 0.f, s_m2 = 0.f;
#pragma unroll
    for (int k = 0; k < 4; k++) {
        // sig via value+slope LUT (L1-resident)
        float mc8 = fminf(fmaxf(mv[k], -8.f), 8.f);
        float f = (mc8 + 8.f) * ((float)LUTN / 16.f);
        int idx = min((int)f, LUTN - 1);
        float frac = f - (float)idx;
        float2 e = __ldg(&g_lut2[idx]);
        sig[k] = fmaf(frac, e.y, e.x);
        // p = softmax(clip(mv)); fixed bound 10
        float mc = fminf(fmaxf(mv[k], -10.f), 10.f);
        e1[k] = __expf(mc - 10.f);
        s_e1 += e1[k];
        s_m += mv[k];
        s_m2 += mv[k] * mv[k];
    }
    float r3[3] = {s_e1, s_m, s_m2};
    block_sumN<3, 4>(r3, red);
    float S1 = r3[0];
    s_m = r3[1]; s_m2 = r3[2];

    float e2[4], s_e2 = 0.f;
#pragma unroll
    for (int k = 0; k < 4; k++) {
        float p = e1[k] / S1;
        float Hent = -p * __logf(p + 1e-6f);
        e2[k] = __expf(fmaf(3.f, Hent, -1.2f));   // 3*Hent <= 3/e < 1.2
        s_e2 += e2[k];
    }
    float r1[1] = {s_e2};
    block_sumN<1, 4>(r1, red);
    float S2 = r1[0];

    float t[4], s_t = 0.f, s_t2 = 0.f;
#pragma unroll
    for (int k = 0; k < 4; k++) {
        t[k] = sig[k] * (e2[k] / S2);
        s_t += t[k];
        s_t2 += t[k] * t[k];
    }
    float4 tv; tv.x = t[0]; tv.y = t[1]; tv.z = t[2]; tv.w = t[3];
    *(float4*)(g_tpre + (size_t)row * Ss + j4) = tv;

    float r2[2] = {s_t, s_t2};
    block_sumN<2, 4>(r2, red);
    if (threadIdx.x == 0) {
        g_partial[row * 4 + 0] = s_m;
        g_partial[row * 4 + 1] = s_m2;
        g_partial[row * 4 + 2] = r2[0];
        g_partial[row * 4 + 3] = r2[1];
        __threadfence();
        int old = atomicAdd(&g_cnt[bb], 1);
        isLast = (old == Ss - 1);
    }
    __syncthreads();

    if (isLast) {
        __threadfence();
        // deterministic strided sum over 512 partial rows
        int tt = threadIdx.x;
        float s0 = 0.f, s1 = 0.f, s2 = 0.f, s3 = 0.f;
        const float* basep = g_partial + (size_t)bb * Ss * 4;
#pragma unroll 1
        for (int r = tt; r < Ss; r += 128) {
            const float* pr = basep + r * 4;
            s0 += pr[0]; s1 += pr[1]; s2 += pr[2]; s3 += pr[3];
        }
        float r4[4] = {s0, s1, s2, s3};
        block_sumN<4, 4>(r4, red);
        if (tt == 0) {
            const float N = (float)(Ss * Ss);
            float e_o = sqrtf(r4[1]) + 1e-4f;
            float e_t = sqrtf(r4[3]) + 1e-4f;
            float gamma = fminf(fmaxf(e_o / e_t, 0.8f), 1.2f);
            float mu_t = r4[2] / N, mu_o = r4[0] / N;
            float var_t = gamma * gamma * (r4[3] / N - mu_t * mu_t);
            float t_std = sqrtf(fmaxf(var_t, 0.01f));
            float var_o = r4[1] / N - mu_o * mu_o;
            float o_std = sqrtf(fmaxf(var_o, 0.01f));
            float gdyn = fminf(fmaxf(o_std / t_std, 0.8f), 1.2f);
            float A = gdyn * gamma;
            g_Acoef[bb] = A;
            g_Ccoef[bb] = mu_o - A * mu_t;
            g_cnt[bb] = 0;          // reset for next launch / graph replay
            __threadfence();
        }
    }
}

// =====================================================================
// blend + softmax: 128 threads x float4, values in regs, single reduction
// grid Bb*Hh*Ss, block 128
// =====================================================================
__global__ __launch_bounds__(128) void softmax_kernel()
{
    __shared__ float red[8];
    int rowid = blockIdx.x;
    int b = rowid >> 12;
    int i = rowid & (Ss - 1);
    int j4 = threadIdx.x * 4;
    const float* srow = g_scores + (size_t)rowid * Ss + j4;
    const float* trow = g_tpre + (((size_t)(b * Ss)) + i) * Ss + j4;
    float A = g_Acoef[b], C = g_Ccoef[b];

    float4 sv = *(const float4*)srow;
    float4 tvv = *(const float4*)trow;
    float sc[4] = {sv.x, sv.y, sv.z, sv.w};
    float tt[4] = {tvv.x, tvv.y, tvv.z, tvv.w};
    float e[4], ls = 0.f;
#pragma unroll
    for (int k = 0; k < 4; k++) {
        float s = fminf(fmaxf(sc[k], -15.f), 15.f);
        float t = fmaf(A, tt[k], C);
        s = fminf(fmaxf(fmaf(0.1f, t, s), -15.f), 15.f);
        e[k] = __expf(s - 15.f);
        ls += e[k];
    }
    float r1[1] = {ls};
    block_sumN<1, 4>(r1, red);
    float inv = 1.f / r1[0];

    __nv_bfloat162 h01, h23, l01, l23;
    float p0 = e[0] * inv, p1 = e[1] * inv, p2 = e[2] * inv, p3 = e[3] * inv;
    h01.x = __float2bfloat16(p0); h01.y = __float2bfloat16(p1);
    h23.x = __float2bfloat16(p2); h23.y = __float2bfloat16(p3);
    l01.x = __float2bfloat16(p0 - __bfloat162float(h01.x));
    l01.y = __float2bfloat16(p1 - __bfloat162float(h01.y));
    l23.x = __float2bfloat16(p2 - __bfloat162float(h23.x));
    l23.y = __float2bfloat16(p3 - __bfloat162float(h23.y));
    bf16* ph = g_phi + (size_t)rowid * Ss + j4;
    bf16* pl = g_plo + (size_t)rowid * Ss + j4;
    *(__nv_bfloat162*)(ph + 0) = h01;
    *(__nv_bfloat162*)(ph + 2) = h23;
    *(__nv_bfloat162*)(pl + 0) = l01;
    *(__nv_bfloat162*)(pl + 2) = l23;
}

// ---------------- launch ----------------
extern "C" void kernel_launch(void* const* d_in, const int* in_sizes, int n_in,
                              void* d_out, int out_size)
{
    const float* x  = (const float*)d_in[0];
    const float* wq = (const float*)d_in[1];
    const float* bq = (const float*)d_in[2];
    const float* wk = (const float*)d_in[3];
    const float* bk = (const float*)d_in[4];
    const float* wv = (const float*)d_in[5];
    const float* bv = (const float*)d_in[6];
    const float* wo = (const float*)d_in[7];
    const float* bo = (const float*)d_in[8];
    const float* w1 = (const float*)d_in[9];
    const float* b1 = (const float*)d_in[10];
    const float* w2 = (const float*)d_in[11];
    const float* b2 = (const float*)d_in[12];
    float* out = (float*)d_out;

    void *pxhi, *pxlo, *pwhi, *pwlo, *pwohi, *pwolo, *pbias, *pqhi, *pqlo, *pchi, *pclo;
    cudaGetSymbolAddress(&pxhi, g_xhi);   cudaGetSymbolAddress(&pxlo, g_xlo);
    cudaGetSymbolAddress(&pwhi, g_whi);   cudaGetSymbolAddress(&pwlo, g_wlo);
    cudaGetSymbolAddress(&pwohi, g_wohi); cudaGetSymbolAddress(&pwolo, g_wolo);
    cudaGetSymbolAddress(&pbias, g_biasqkv);
    cudaGetSymbolAddress(&pqhi, g_qhi);   cudaGetSymbolAddress(&pqlo, g_qlo);
    cudaGetSymbolAddress(&pchi, g_chi);   cudaGetSymbolAddress(&pclo, g_clo);

    cudaFuncSetAttribute(gemm_big<0>, cudaFuncAttributeMaxDynamicSharedMemorySize, SMEM_BIG);
    cudaFuncSetAttribute(gemm_big<1>, cudaFuncAttributeMaxDynamicSharedMemorySize, SMEM_BIG);
    cudaFuncSetAttribute(gemm_scores_mma, cudaFuncAttributeMaxDynamicSharedMemorySize, SMEM_SM);
    cudaFuncSetAttribute(gemm_attnv_mma, cudaFuncAttributeMaxDynamicSharedMemorySize, SMEM_SM);

    // conversions + bias + LUT in one launch
    conv_all<<<8207, 256>>>(x, wq, wk, wv, wo, bq, bk, bv, w1, b1, w2, b2);

    // fused QKV projection (N = 1536)
    gemm_big<0><<<dim3(12, 16), 256, SMEM_BIG>>>(
        (const bf16*)pxhi, (const bf16*)pxlo, (const bf16*)pwhi, (const bf16*)pwlo,
        (const float*)pbias, nullptr, (bf16*)pqhi, (bf16*)pqlo);

    // scores with fused partial head-mean (4 heads per CTA, 2 halves)
    gemm_scores_mma<<<dim3(8, 8, Bb * 2), 256, SMEM_SM>>>();
    // transform computes per-batch scalars in its last block
    transform_kernel<<<Bb * Ss, 128>>>();
    softmax_kernel<<<Bb * Hh * Ss, 128>>>();
    gemm_attnv_mma<<<dim3(8, Bb * Hh), 256, SMEM_SM>>>();

    // output projection
    gemm_big<1><<<dim3(4, 16), 256, SMEM_BIG>>>(
        (const bf16*)pchi, (const bf16*)pclo, (const bf16*)pwohi, (const bf16*)pwolo,
        bo, out, nullptr, nullptr);
}

// round 14
// speedup vs baseline: 1.2147x; 1.2147x over previous
#include <cuda_runtime.h>
#include <cuda_bf16.h>
#include <cstdint>
#include <math.h>

typedef __nv_bfloat16 bf16;

#define Bb   4
#define Ss   512
#define Ee   512
#define Hh   8
#define DHd  64
#define HIDh 128
#define MTOT 2048
#define SZQ  (2048 * 512)
#define SCsz ((size_t)Bb * Hh * Ss * Ss)
#define LUTN 2048

// ---- scratch (allocation-free: __device__ globals) ----
__device__ bf16  g_xhi[MTOT * Ee], g_xlo[MTOT * Ee];
__device__ bf16  g_whi[3 * Ee * Ee], g_wlo[3 * Ee * Ee];
__device__ bf16  g_wohi[Ee * Ee], g_wolo[Ee * Ee];
__device__ float g_biasqkv[3 * Ee];
__device__ bf16  g_qhi[3 * SZQ], g_qlo[3 * SZQ];   // q|k|v splits
__device__ float g_scores[SCsz];
__device__ bf16  g_phi[SCsz], g_plo[SCsz];
__device__ float g_tpre[(size_t)Bb * Ss * Ss];
__device__ bf16  g_chi[MTOT * Ee], g_clo[MTOT * Ee];
__device__ float g_partial[Bb * Ss * 4];
__device__ float g_Acoef[Bb];
__device__ float g_Ccoef[Bb];
__device__ float2 g_lut2[LUTN];     // {sig(i), sig(i+1)-sig(i)}

// =====================================================================
// low-level helpers
// =====================================================================
__device__ __forceinline__ uint32_t smem_u32(const void* p) {
    uint32_t a;
    asm("{ .reg .u64 t; cvta.to.shared.u64 t, %1; cvt.u32.u64 %0, t; }" : "=r"(a) : "l"(p));
    return a;
}
__device__ __forceinline__ void cp16(uint32_t dst, const void* src) {
    asm volatile("cp.async.cg.shared.global [%0], [%1], 16;" :: "r"(dst), "l"(src));
}
__device__ __forceinline__ void cp_commit() {
    asm volatile("cp.async.commit_group;" ::: "memory");
}
__device__ __forceinline__ void ldsm4(uint32_t addr, uint32_t& r0, uint32_t& r1,
                                      uint32_t& r2, uint32_t& r3) {
    asm volatile("ldmatrix.sync.aligned.m8n8.x4.shared.b16 {%0,%1,%2,%3}, [%4];"
                 : "=r"(r0), "=r"(r1), "=r"(r2), "=r"(r3) : "r"(addr));
}
__device__ __forceinline__ void ldsm4t(uint32_t addr, uint32_t& r0, uint32_t& r1,
                                       uint32_t& r2, uint32_t& r3) {
    asm volatile("ldmatrix.sync.aligned.m8n8.x4.trans.shared.b16 {%0,%1,%2,%3}, [%4];"
                 : "=r"(r0), "=r"(r1), "=r"(r2), "=r"(r3) : "r"(addr));
}
__device__ __forceinline__ void mma16816(float* d, const uint32_t* a, uint32_t b0, uint32_t b1) {
    asm volatile("mma.sync.aligned.m16n8k16.row.col.f32.bf16.bf16.f32 "
                 "{%0,%1,%2,%3}, {%4,%5,%6,%7}, {%8,%9}, {%0,%1,%2,%3};"
                 : "+f"(d[0]), "+f"(d[1]), "+f"(d[2]), "+f"(d[3])
                 : "r"(a[0]), "r"(a[1]), "r"(a[2]), "r"(a[3]), "r"(b0), "r"(b1));
}

// swizzled smem offset: 128B rows, 16B chunks, c8 ^= (r & 7)
#define SWZ(r, c8) ((((uint32_t)(r)) << 7) + ((((uint32_t)(c8)) ^ ((uint32_t)(r) & 7)) << 4))

__device__ __forceinline__ void load_tile128(uint32_t dst, const bf16* __restrict__ src,
                                             int tid) {
#pragma unroll
    for (int i = 0; i < 4; i++) {
        int ch = tid + i * 256;
        int r = ch >> 3, c8 = ch & 7;
        cp16(dst + SWZ(r, c8), src + (size_t)r * 512 + c8 * 8);
    }
}
__device__ __forceinline__ void load_tile64(uint32_t dst, const bf16* __restrict__ src,
                                            int tid) {
#pragma unroll
    for (int i = 0; i < 2; i++) {
        int ch = tid + i * 256;
        int r = ch >> 3, c8 = ch & 7;
        cp16(dst + SWZ(r, c8), src + (size_t)r * 512 + c8 * 8);
    }
}

// warp tile 32(m) x 32(n), B n-major (NT), acc[2][4][4]  -- 128x64 CTA tiles
__device__ __forceinline__ void mma_slab_m32n32_nt(uint32_t As, uint32_t Bs,
                                                   int warp_m0, int warp_n0, int lane,
                                                   float acc[2][4][4]) {
#pragma unroll
    for (int kk = 0; kk < 4; kk++) {
        uint32_t a[2][4];
#pragma unroll
        for (int mi = 0; mi < 2; mi++) {
            int r = warp_m0 + mi * 16 + (lane & 15);
            uint32_t addr = As + (r << 7) + ((((kk << 1) + (lane >> 4)) ^ (r & 7)) << 4);
            ldsm4(addr, a[mi][0], a[mi][1], a[mi][2], a[mi][3]);
        }
#pragma unroll
        for (int pr = 0; pr < 2; pr++) {
            int nr = warp_n0 + pr * 16 + (lane & 7) + ((lane >> 4) << 3);
            uint32_t addr = Bs + (nr << 7) + ((((kk << 1) + ((lane >> 3) & 1)) ^ (nr & 7)) << 4);
            uint32_t b0, b1, b2, b3;
            ldsm4(addr, b0, b1, b2, b3);
#pragma unroll
            for (int mi = 0; mi < 2; mi++) {
                mma16816(acc[mi][2 * pr + 0], a[mi], b0, b1);
                mma16816(acc[mi][2 * pr + 1], a[mi], b2, b3);
            }
        }
    }
}

// warp tile 16(m) x 32(n), B n-major (NT), acc[4][4]
__device__ __forceinline__ void mma_slab_m16n32_nt(uint32_t As, uint32_t Bs,
                                                   int warp_m0, int warp_n0, int lane,
                                                   float acc[4][4]) {
#pragma unroll
    for (int kk = 0; kk < 4; kk++) {
        uint32_t a[4];
        {
            int r = warp_m0 + (lane & 15);
            uint32_t addr = As + (r << 7) + ((((kk << 1) + (lane >> 4)) ^ (r & 7)) << 4);
            ldsm4(addr, a[0], a[1], a[2], a[3]);
        }
#pragma unroll
        for (int pr = 0; pr < 2; pr++) {
            int nr = warp_n0 + pr * 16 + (lane & 7) + ((lane >> 4) << 3);
            uint32_t addr = Bs + (nr << 7) + ((((kk << 1) + ((lane >> 3) & 1)) ^ (nr & 7)) << 4);
            uint32_t b0, b1, b2, b3;
            ldsm4(addr, b0, b1, b2, b3);
            mma16816(acc[2 * pr + 0], a, b0, b1);
            mma16816(acc[2 * pr + 1], a, b2, b3);
        }
    }
}

// warp tile 16(m) x 32(n), B k-major (trans), acc[4][4]
__device__ __forceinline__ void mma_slab_m16n32_t(uint32_t As, uint32_t Bs,
                                                  int warp_m0, int warp_n0, int lane,
                                                  float acc[4][4]) {
#pragma unroll
    for (int kk = 0; kk < 4; kk++) {
        uint32_t a[4];
        {
            int r = warp_m0 + (lane & 15);
            uint32_t addr = As + (r << 7) + ((((kk << 1) + (lane >> 4)) ^ (r & 7)) << 4);
            ldsm4(addr, a[0], a[1], a[2], a[3]);
        }
#pragma unroll
        for (int pr = 0; pr < 2; pr++) {
            int kr = kk * 16 + (lane & 15);
            int c8 = ((warp_n0 + pr * 16) >> 3) + (lane >> 4);
            uint32_t addr = Bs + (kr << 7) + ((c8 ^ (kr & 7)) << 4);
            uint32_t b0, b1, b2, b3;
            ldsm4t(addr, b0, b1, b2, b3);
            mma16816(acc[2 * pr + 0], a, b0, b1);
            mma16816(acc[2 * pr + 1], a, b2, b3);
        }
    }
}

#define STG_MID   24576
#define SMEM_MID  (3 * STG_MID)
#define STG_SM    16384
#define SMEM_SM   (3 * STG_SM)

// =====================================================================
// big NT GEMM, CTA tile 128(m) x 64(n), warp 32x32, 3-stage
// MODE 0: qkv split-out (N=1536 virtual). MODE 1: oproj fp32 out.
// =====================================================================
template <int MODE>
__global__ __launch_bounds__(256) void gemm_big(
    const bf16* __restrict__ Ahi, const bf16* __restrict__ Alo,
    const bf16* __restrict__ Bhi, const bf16* __restrict__ Blo,
    const float* __restrict__ bias, float* __restrict__ outf,
    bf16* __restrict__ ohi, bf16* __restrict__ olo)
{
    extern __shared__ char dsm[];
    const uint32_t sb = smem_u32(dsm);
    const int tid = threadIdx.x;
    const int lane = tid & 31, w = tid >> 5;
    const int warp_m0 = (w >> 1) * 32, warp_n0 = (w & 1) * 32;
    const int bn = blockIdx.x * 64, bm = blockIdx.y * 128;
    const int NS = 24;

    float acc[2][4][4];
#pragma unroll
    for (int mi = 0; mi < 2; mi++)
#pragma unroll
        for (int nf = 0; nf < 4; nf++)
#pragma unroll
            for (int q = 0; q < 4; q++) acc[mi][nf][q] = 0.f;

#define LOAD_SLAB(s, st)                                                        \
    do {                                                                        \
        int part = (s) >> 3;                                                    \
        int k0 = ((s) & 7) * 64;                                                \
        const bf16* Asrc = ((part == 2) ? Alo : Ahi) + (size_t)bm * 512 + k0;   \
        const bf16* Bsrc = ((part == 1) ? Blo : Bhi) + (size_t)bn * 512 + k0;   \
        load_tile128(sb + (st) * STG_MID, Asrc, tid);                           \
        load_tile64(sb + (st) * STG_MID + 16384, Bsrc, tid);                    \
        cp_commit();                                                            \
    } while (0)

    LOAD_SLAB(0, 0);
    LOAD_SLAB(1, 1);
#pragma unroll 1
    for (int s = 0; s < NS; s++) {
        if (s + 2 < NS) {
            LOAD_SLAB(s + 2, (s + 2) % 3);
            asm volatile("cp.async.wait_group 2;" ::: "memory");
        } else if (s + 1 < NS) {
            asm volatile("cp.async.wait_group 1;" ::: "memory");
        } else {
            asm volatile("cp.async.wait_group 0;" ::: "memory");
        }
        __syncthreads();
        uint32_t st = sb + (s % 3) * STG_MID;
        mma_slab_m32n32_nt(st, st + 16384, warp_m0, warp_n0, lane, acc);
        __syncthreads();
    }
#undef LOAD_SLAB

    const int mrow = lane >> 2, ncol = 2 * (lane & 3);
#pragma unroll
    for (int mi = 0; mi < 2; mi++) {
#pragma unroll
        for (int nf = 0; nf < 4; nf++) {
            int n_g = bn + warp_n0 + nf * 8 + ncol;
            float2 bb = *(const float2*)(bias + n_g);
#pragma unroll
            for (int hh = 0; hh < 2; hh++) {
                int m = bm + warp_m0 + mi * 16 + mrow + hh * 8;
                float v0 = acc[mi][nf][hh * 2 + 0] + bb.x;
                float v1 = acc[mi][nf][hh * 2 + 1] + bb.y;
                if (MODE == 0) {
                    int seg = n_g >> 9, col = n_g & 511;
                    bf16 h0 = __float2bfloat16(v0), h1 = __float2bfloat16(v1);
                    __nv_bfloat162 hv; hv.x = h0; hv.y = h1;
                    __nv_bfloat162 lv;
                    lv.x = __float2bfloat16(v0 - __bfloat162float(h0));
                    lv.y = __float2bfloat16(v1 - __bfloat162float(h1));
                    *(__nv_bfloat162*)(ohi + (size_t)seg * SZQ + (size_t)m * 512 + col) = hv;
                    *(__nv_bfloat162*)(olo + (size_t)seg * SZQ + (size_t)m * 512 + col) = lv;
                } else {
                    float2 o; o.x = v0; o.y = v1;
                    *(float2*)(outf + (size_t)m * 512 + n_g) = o;
                }
            }
        }
    }
}

// =====================================================================
// scores: per (b,h) S = Q K^T; CTA tile 64x64, warp 16x32 (round-11)
// grid (8, 8, 32)
// =====================================================================
__global__ __launch_bounds__(256) void gemm_scores_mma()
{
    extern __shared__ char dsm[];
    const uint32_t sb = smem_u32(dsm);
    const int tid = threadIdx.x;
    const int lane = tid & 31, w = tid >> 5;
    const int warp_m0 = (w >> 1) * 16, warp_n0 = (w & 1) * 32;
    int bh = blockIdx.z;
    int b = bh >> 3, h = bh & 7;
    int bn = blockIdx.x * 64, bm = blockIdx.y * 64;
    const int NS = 3;

    float acc[4][4];
#pragma unroll
    for (int nf = 0; nf < 4; nf++)
#pragma unroll
        for (int q = 0; q < 4; q++) acc[nf][q] = 0.f;

#define LOAD_SLAB(s, st)                                                                    \
    do {                                                                                    \
        const bf16* Asrc = ((s) == 2 ? g_qlo : g_qhi) + (size_t)(b * 512 + bm) * 512 + h * 64; \
        const bf16* Bsrc = ((s) == 1 ? g_qlo : g_qhi) + SZQ + (size_t)(b * 512 + bn) * 512 + h * 64; \
        load_tile64(sb + (st) * STG_SM, Asrc, tid);                                         \
        load_tile64(sb + (st) * STG_SM + 8192, Bsrc, tid);                                  \
        cp_commit();                                                                        \
    } while (0)

    LOAD_SLAB(0, 0);
    LOAD_SLAB(1, 1);
#pragma unroll 1
    for (int s = 0; s < NS; s++) {
        if (s + 2 < NS) {
            LOAD_SLAB(s + 2, (s + 2) % 3);
            asm volatile("cp.async.wait_group 2;" ::: "memory");
        } else if (s + 1 < NS) {
            asm volatile("cp.async.wait_group 1;" ::: "memory");
        } else {
            asm volatile("cp.async.wait_group 0;" ::: "memory");
        }
        __syncthreads();
        uint32_t st = sb + (s % 3) * STG_SM;
        mma_slab_m16n32_nt(st, st + 8192, warp_m0, warp_n0, lane, acc);
        __syncthreads();
    }
#undef LOAD_SLAB

    float* Cp = g_scores + (size_t)bh * Ss * Ss;
    const int mrow = lane >> 2, ncol = 2 * (lane & 3);
#pragma unroll
    for (int nf = 0; nf < 4; nf++) {
        int n_g = bn + warp_n0 + nf * 8 + ncol;
#pragma unroll
        for (int hh = 0; hh < 2; hh++) {
            int m = bm + warp_m0 + mrow + hh * 8;
            float2 o;
            o.x = acc[nf][hh * 2 + 0];
            o.y = acc[nf][hh * 2 + 1];
            *(float2*)(Cp + (size_t)m * 512 + n_g) = o;
        }
    }
}

// =====================================================================
// attn*V: per (b,h) ctx = P V; CTA tile 64(m)x64(n), warp 16x32
// =====================================================================
__global__ __launch_bounds__(256) void gemm_attnv_mma()
{
    extern __shared__ char dsm[];
    const uint32_t sb = smem_u32(dsm);
    const int tid = threadIdx.x;
    const int lane = tid & 31, w = tid >> 5;
    const int warp_m0 = (w >> 1) * 16, warp_n0 = (w & 1) * 32;
    int bh = blockIdx.y;
    int b = bh >> 3, h = bh & 7;
    int bm = blockIdx.x * 64;
    const size_t pbase = (size_t)bh * Ss * Ss;
    const int NS = 24;

    float acc[4][4];
#pragma unroll
    for (int nf = 0; nf < 4; nf++)
#pragma unroll
        for (int q = 0; q < 4; q++) acc[nf][q] = 0.f;

#define LOAD_SLAB(s, st)                                                                     \
    do {                                                                                     \
        int part = (s) >> 3;                                                                 \
        int k0 = ((s) & 7) * 64;                                                             \
        const bf16* Asrc = ((part == 2) ? g_plo : g_phi) + pbase + (size_t)bm * 512 + k0;    \
        const bf16* Bsrc = ((part == 1) ? g_qlo : g_qhi) + 2 * (size_t)SZQ                   \
                           + (size_t)(b * 512 + k0) * 512 + h * 64;                          \
        load_tile64(sb + (st) * STG_SM, Asrc, tid);                                          \
        load_tile64(sb + (st) * STG_SM + 8192, Bsrc, tid);                                   \
        cp_commit();                                                                         \
    } while (0)

    LOAD_SLAB(0, 0);
    LOAD_SLAB(1, 1);
#pragma unroll 1
    for (int s = 0; s < NS; s++) {
        if (s + 2 < NS) {
            LOAD_SLAB(s + 2, (s + 2) % 3);
            asm volatile("cp.async.wait_group 2;" ::: "memory");
        } else if (s + 1 < NS) {
            asm volatile("cp.async.wait_group 1;" ::: "memory");
        } else {
            asm volatile("cp.async.wait_group 0;" ::: "memory");
        }
        __syncthreads();
        uint32_t st = sb + (s % 3) * STG_SM;
        mma_slab_m16n32_t(st, st + 8192, warp_m0, warp_n0, lane, acc);
        __syncthreads();
    }
#undef LOAD_SLAB

    const int mrow = lane >> 2, ncol = 2 * (lane & 3);
#pragma unroll
    for (int nf = 0; nf < 4; nf++) {
        int n_g = h * 64 + warp_n0 + nf * 8 + ncol;
#pragma unroll
        for (int hh = 0; hh < 2; hh++) {
            int m = b * 512 + bm + warp_m0 + mrow + hh * 8;
            float v0 = acc[nf][hh * 2 + 0];
            float v1 = acc[nf][hh * 2 + 1];
            bf16 h0 = __float2bfloat16(v0), h1 = __float2bfloat16(v1);
            __nv_bfloat162 hv; hv.x = h0; hv.y = h1;
            __nv_bfloat162 lv;
            lv.x = __float2bfloat16(v0 - __bfloat162float(h0));
            lv.y = __float2bfloat16(v1 - __bfloat162float(h1));
            *(__nv_bfloat162*)(g_chi + (size_t)m * 512 + n_g) = hv;
            *(__nv_bfloat162*)(g_clo + (size_t)m * 512 + n_g) = lv;
        }
    }
}

// =====================================================================
// reductions
// =====================================================================
__device__ __forceinline__ float warp_sum(float v) {
#pragma unroll
    for (int o = 16; o; o >>= 1) v += __shfl_xor_sync(0xffffffffu, v, o);
    return v;
}
template <int NV, int NW>
__device__ __forceinline__ void block_sumN(float* v, float* red) {
    int lane = threadIdx.x & 31, w = threadIdx.x >> 5;
#pragma unroll
    for (int i = 0; i < NV; i++) v[i] = warp_sum(v[i]);
    if (lane == 0)
#pragma unroll
        for (int i = 0; i < NV; i++) red[w * NV + i] = v[i];
    __syncthreads();
    if (w == 0) {
#pragma unroll
        for (int i = 0; i < NV; i++) {
            float x = (lane < NW) ? red[lane * NV + i] : 0.f;
            x = warp_sum(x);
            if (lane == 0) red[i] = x;
        }
    }
    __syncthreads();
#pragma unroll
    for (int i = 0; i < NV; i++) v[i] = red[i];
    __syncthreads();
}

// =====================================================================
// exact sig(mv) evaluator (used only by LUT build)
// =====================================================================
__device__ __forceinline__ float sig_exact(float mv, const float* __restrict__ w1,
                                           const float* __restrict__ b1,
                                           const float* __restrict__ w2, float b2v)
{
    float scaled = mv * 0.05f;
    float av = 0.f;
#pragma unroll 8
    for (int hh = 0; hh < HIDh; hh++) {
        float hv = fmaf(scaled, w1[hh], b1[hh]);
        hv = fminf(fmaxf(hv, 0.f), 5.f);
        av = fmaf(hv, w2[hh], av);
    }
    av += b2v;
    av = fminf(fmaxf(av, -5.f), 5.f);
    float taylor = fminf(fmaxf(fmaf(av, 2.5f, 1.f), 0.5f), 1.5f);
    return 1.f / (1.f + __expf(-taylor));
}

// =====================================================================
// fused conversion kernel, float4 per thread
// grid = 1024(x) + 4*256(w) + 7(bias) + 8(LUT) = 2063 blocks of 256
// =====================================================================
__device__ __forceinline__ void conv4(const float* __restrict__ src, bf16* hi, bf16* lo,
                                      float scale, int i4)
{
    float4 a = *(const float4*)(src + i4 * 4);
    a.x *= scale; a.y *= scale; a.z *= scale; a.w *= scale;
    __nv_bfloat162 h01, h23, l01, l23;
    h01.x = __float2bfloat16(a.x); h01.y = __float2bfloat16(a.y);
    h23.x = __float2bfloat16(a.z); h23.y = __float2bfloat16(a.w);
    l01.x = __float2bfloat16(a.x - __bfloat162float(h01.x));
    l01.y = __float2bfloat16(a.y - __bfloat162float(h01.y));
    l23.x = __float2bfloat16(a.z - __bfloat162float(h23.x));
    l23.y = __float2bfloat16(a.w - __bfloat162float(h23.y));
    *(__nv_bfloat162*)(hi + i4 * 4 + 0) = h01;
    *(__nv_bfloat162*)(hi + i4 * 4 + 2) = h23;
    *(__nv_bfloat162*)(lo + i4 * 4 + 0) = l01;
    *(__nv_bfloat162*)(lo + i4 * 4 + 2) = l23;
}

__global__ __launch_bounds__(256) void conv_all(
    const float* __restrict__ x,
    const float* __restrict__ wq, const float* __restrict__ wk,
    const float* __restrict__ wv, const float* __restrict__ wo,
    const float* __restrict__ bq, const float* __restrict__ bk,
    const float* __restrict__ bv,
    const float* __restrict__ w1, const float* __restrict__ b1,
    const float* __restrict__ w2, const float* __restrict__ b2p)
{
    int bid = blockIdx.x;
    int tid = threadIdx.x;
    if (bid < 1024) {
        conv4(x, g_xhi, g_xlo, 1.f, bid * 256 + tid);
    } else if (bid < 1280) {
        conv4(wq, g_whi, g_wlo, 0.125f, (bid - 1024) * 256 + tid);
    } else if (bid < 1536) {
        conv4(wk, g_whi + Ee * Ee, g_wlo + Ee * Ee, 1.f, (bid - 1280) * 256 + tid);
    } else if (bid < 1792) {
        conv4(wv, g_whi + 2 * Ee * Ee, g_wlo + 2 * Ee * Ee, 1.f, (bid - 1536) * 256 + tid);
    } else if (bid < 2048) {
        conv4(wo, g_wohi, g_wolo, 1.f, (bid - 1792) * 256 + tid);
    } else if (bid < 2055) {
        int j = (bid - 2048) * 256 + tid;
        if (j < 1536) {
            float v = (j < 512) ? bq[j] * 0.125f : (j < 1024 ? bk[j - 512] : bv[j - 1024]);
            g_biasqkv[j] = v;
        }
    } else {
        int j = (bid - 2055) * 256 + tid;
        if (j < LUTN) {
            float b2v = b2p[0];
            float step = 16.f / (float)LUTN;
            float m0 = -8.f + step * (float)j;
            float s0 = sig_exact(m0, w1, b1, w2, b2v);
            float s1 = sig_exact(m0 + step, w1, b1, w2, b2v);
            float2 e; e.x = s0; e.y = s1 - s0;
            g_lut2[j] = e;
        }
    }
}

// =====================================================================
// transform: 128 threads x float4; head-mean + LUT sig + entropy + stats
// grid Bb*Ss, block 128      (round-11 version)
// =====================================================================
__global__ __launch_bounds__(128) void transform_kernel()
{
    __shared__ float red[16];
    int row = blockIdx.x;
    int b = row >> 9, i = row & (Ss - 1);
    int j4 = threadIdx.x * 4;

    const float* base = g_scores + (((size_t)(b * Hh)) * Ss + i) * Ss + j4;
    float mv[4] = {0.f, 0.f, 0.f, 0.f};
#pragma unroll
    for (int h = 0; h < Hh; h++) {
        float4 v = *(const float4*)(base + (size_t)h * Ss * Ss);
        mv[0] += fminf(fmaxf(v.x, -15.f), 15.f);
        mv[1] += fminf(fmaxf(v.y, -15.f), 15.f);
        mv[2] += fminf(fmaxf(v.z, -15.f), 15.f);
        mv[3] += fminf(fmaxf(v.w, -15.f), 15.f);
    }
    float sig[4], e1[4];
    float s_e1 = 0.f, s_m = 0.f, s_m2 = 0.f;
#pragma unroll
    for (int k = 0; k < 4; k++) {
        mv[k] *= 0.125f;
        float mc8 = fminf(fmaxf(mv[k], -8.f), 8.f);
        float f = (mc8 + 8.f) * ((float)LUTN / 16.f);
        int idx = min((int)f, LUTN - 1);
        float frac = f - (float)idx;
        float2 e = __ldg(&g_lut2[idx]);
        sig[k] = fmaf(frac, e.y, e.x);
        float mc = fminf(fmaxf(mv[k], -10.f), 10.f);
        e1[k] = __expf(mc - 10.f);
        s_e1 += e1[k];
        s_m += mv[k];
        s_m2 += mv[k] * mv[k];
    }
    float r3[3] = {s_e1, s_m, s_m2};
    block_sumN<3, 4>(r3, red);
    float S1 = r3[0];
    s_m = r3[1]; s_m2 = r3[2];

    float e2[4], s_e2 = 0.f;
#pragma unroll
    for (int k = 0; k < 4; k++) {
        float p = e1[k] / S1;
        float Hent = -p * __logf(p + 1e-6f);
        e2[k] = __expf(fmaf(3.f, Hent, -1.2f));   // 3*Hent <= 3/e < 1.2
        s_e2 += e2[k];
    }
    float r1[1] = {s_e2};
    block_sumN<1, 4>(r1, red);
    float S2 = r1[0];

    float t[4], s_t = 0.f, s_t2 = 0.f;
#pragma unroll
    for (int k = 0; k < 4; k++) {
        t[k] = sig[k] * (e2[k] / S2);
        s_t += t[k];
        s_t2 += t[k] * t[k];
    }
    float4 tv; tv.x = t[0]; tv.y = t[1]; tv.z = t[2]; tv.w = t[3];
    *(float4*)(g_tpre + (size_t)row * Ss + j4) = tv;

    float r2[2] = {s_t, s_t2};
    block_sumN<2, 4>(r2, red);
    if (threadIdx.x == 0) {
        g_partial[row * 4 + 0] = s_m;
        g_partial[row * 4 + 1] = s_m2;
        g_partial[row * 4 + 2] = r2[0];
        g_partial[row * 4 + 3] = r2[1];
    }
}

__global__ __launch_bounds__(512) void scalars_kernel()
{
    __shared__ float red[64];
    int b = blockIdx.x;
    int t = threadIdx.x;
    const float* pr = g_partial + (size_t)(b * Ss + t) * 4;
    float r4[4] = {pr[0], pr[1], pr[2], pr[3]};
    block_sumN<4, 16>(r4, red);
    if (t == 0) {
        const float N = (float)(Ss * Ss);
        float s0 = r4[0], s1 = r4[1], s2 = r4[2], s3 = r4[3];
        float e_o = sqrtf(s1) + 1e-4f;
        float e_t = sqrtf(s3) + 1e-4f;
        float gamma = fminf(fmaxf(e_o / e_t, 0.8f), 1.2f);
        float mu_t = s2 / N, mu_o = s0 / N;
        float var_t = gamma * gamma * (s3 / N - mu_t * mu_t);
        float t_std = sqrtf(fmaxf(var_t, 0.01f));
        float var_o = s1 / N - mu_o * mu_o;
        float o_std = sqrtf(fmaxf(var_o, 0.01f));
        float gdyn = fminf(fmaxf(o_std / t_std, 0.8f), 1.2f);
        float A = gdyn * gamma;
        g_Acoef[b] = A;
        g_Ccoef[b] = mu_o - A * mu_t;
    }
}

// =====================================================================
// blend + softmax: 128 threads x float4, values in regs, single reduction
// grid Bb*Hh*Ss, block 128
// =====================================================================
__global__ __launch_bounds__(128) void softmax_kernel()
{
    __shared__ float red[8];
    int rowid = blockIdx.x;
    int b = rowid >> 12;
    int i = rowid & (Ss - 1);
    int j4 = threadIdx.x * 4;
    const float* srow = g_scores + (size_t)rowid * Ss + j4;
    const float* trow = g_tpre + (((size_t)(b * Ss)) + i) * Ss + j4;
    float A = g_Acoef[b], C = g_Ccoef[b];

    float4 sv = *(const float4*)srow;
    float4 tvv = *(const float4*)trow;
    float sc[4] = {sv.x, sv.y, sv.z, sv.w};
    float tt[4] = {tvv.x, tvv.y, tvv.z, tvv.w};
    float e[4], ls = 0.f;
#pragma unroll
    for (int k = 0; k < 4; k++) {
        float s = fminf(fmaxf(sc[k], -15.f), 15.f);
        float t = fmaf(A, tt[k], C);
        s = fminf(fmaxf(fmaf(0.1f, t, s), -15.f), 15.f);
        e[k] = __expf(s - 15.f);
        ls += e[k];
    }
    float r1[1] = {ls};
    block_sumN<1, 4>(r1, red);
    float inv = 1.f / r1[0];

    __nv_bfloat162 h01, h23, l01, l23;
    float p0 = e[0] * inv, p1 = e[1] * inv, p2 = e[2] * inv, p3 = e[3] * inv;
    h01.x = __float2bfloat16(p0); h01.y = __float2bfloat16(p1);
    h23.x = __float2bfloat16(p2); h23.y = __float2bfloat16(p3);
    l01.x = __float2bfloat16(p0 - __bfloat162float(h01.x));
    l01.y = __float2bfloat16(p1 - __bfloat162float(h01.y));
    l23.x = __float2bfloat16(p2 - __bfloat162float(h23.x));
    l23.y = __float2bfloat16(p3 - __bfloat162float(h23.y));
    bf16* ph = g_phi + (size_t)rowid * Ss + j4;
    bf16* pl = g_plo + (size_t)rowid * Ss + j4;
    *(__nv_bfloat162*)(ph + 0) = h01;
    *(__nv_bfloat162*)(ph + 2) = h23;
    *(__nv_bfloat162*)(pl + 0) = l01;
    *(__nv_bfloat162*)(pl + 2) = l23;
}

// ---------------- launch ----------------
extern "C" void kernel_launch(void* const* d_in, const int* in_sizes, int n_in,
                              void* d_out, int out_size)
{
    const float* x  = (const float*)d_in[0];
    const float* wq = (const float*)d_in[1];
    const float* bq = (const float*)d_in[2];
    const float* wk = (const float*)d_in[3];
    const float* bk = (const float*)d_in[4];
    const float* wv = (const float*)d_in[5];
    const float* bv = (const float*)d_in[6];
    const float* wo = (const float*)d_in[7];
    const float* bo = (const float*)d_in[8];
    const float* w1 = (const float*)d_in[9];
    const float* b1 = (const float*)d_in[10];
    const float* w2 = (const float*)d_in[11];
    const float* b2 = (const float*)d_in[12];
    float* out = (float*)d_out;

    void *pxhi, *pxlo, *pwhi, *pwlo, *pwohi, *pwolo, *pbias, *pqhi, *pqlo, *pchi, *pclo;
    cudaGetSymbolAddress(&pxhi, g_xhi);   cudaGetSymbolAddress(&pxlo, g_xlo);
    cudaGetSymbolAddress(&pwhi, g_whi);   cudaGetSymbolAddress(&pwlo, g_wlo);
    cudaGetSymbolAddress(&pwohi, g_wohi); cudaGetSymbolAddress(&pwolo, g_wolo);
    cudaGetSymbolAddress(&pbias, g_biasqkv);
    cudaGetSymbolAddress(&pqhi, g_qhi);   cudaGetSymbolAddress(&pqlo, g_qlo);
    cudaGetSymbolAddress(&pchi, g_chi);   cudaGetSymbolAddress(&pclo, g_clo);

    cudaFuncSetAttribute(gemm_big<0>, cudaFuncAttributeMaxDynamicSharedMemorySize, SMEM_MID);
    cudaFuncSetAttribute(gemm_big<1>, cudaFuncAttributeMaxDynamicSharedMemorySize, SMEM_MID);
    cudaFuncSetAttribute(gemm_scores_mma, cudaFuncAttributeMaxDynamicSharedMemorySize, SMEM_SM);
    cudaFuncSetAttribute(gemm_attnv_mma, cudaFuncAttributeMaxDynamicSharedMemorySize, SMEM_SM);

    // conversions + bias + LUT in one launch (float4 per thread)
    conv_all<<<2063, 256>>>(x, wq, wk, wv, wo, bq, bk, bv, w1, b1, w2, b2);

    // fused QKV projection (N = 1536), 128x64 tiles -> 384 CTAs
    gemm_big<0><<<dim3(24, 16), 256, SMEM_MID>>>(
        (const bf16*)pxhi, (const bf16*)pxlo, (const bf16*)pwhi, (const bf16*)pwlo,
        (const float*)pbias, nullptr, (bf16*)pqhi, (bf16*)pqlo);

    gemm_scores_mma<<<dim3(8, 8, Bb * Hh), 256, SMEM_SM>>>();
    transform_kernel<<<Bb * Ss, 128>>>();
    scalars_kernel<<<Bb, 512>>>();
    softmax_kernel<<<Bb * Hh * Ss, 128>>>();
    gemm_attnv_mma<<<dim3(8, Bb * Hh), 256, SMEM_SM>>>();

    // output projection, 128x64 tiles -> 128 CTAs
    gemm_big<1><<<dim3(8, 16), 256, SMEM_MID>>>(
        (const bf16*)pchi, (const bf16*)pclo, (const bf16*)pwohi, (const bf16*)pwolo,
        bo, out, nullptr, nullptr);
}

// round 15
// speedup vs baseline: 1.2383x; 1.0194x over previous
#include <cuda_runtime.h>
#include <cuda_bf16.h>
#include <cstdint>
#include <math.h>

typedef __nv_bfloat16 bf16;

#define Bb   4
#define Ss   512
#define Ee   512
#define Hh   8
#define DHd  64
#define HIDh 128
#define MTOT 2048
#define SZQ  (2048 * 512)
#define SCsz ((size_t)Bb * Hh * Ss * Ss)
#define LUTN 2048

// ---- scratch (allocation-free: __device__ globals) ----
__device__ bf16  g_xhi[MTOT * Ee], g_xlo[MTOT * Ee];
__device__ bf16  g_whi[3 * Ee * Ee], g_wlo[3 * Ee * Ee];
__device__ bf16  g_wohi[Ee * Ee], g_wolo[Ee * Ee];
__device__ float g_biasqkv[3 * Ee];
__device__ bf16  g_qhi[3 * SZQ], g_qlo[3 * SZQ];   // q|k|v splits
__device__ float g_scores[SCsz];
__device__ bf16  g_phi[SCsz], g_plo[SCsz];
__device__ float g_tpre[(size_t)Bb * Ss * Ss];
__device__ bf16  g_chi[MTOT * Ee], g_clo[MTOT * Ee];
__device__ float g_partial[Bb * Ss * 4];
__device__ float g_Acoef[Bb];
__device__ float g_Ccoef[Bb];
__device__ float2 g_lut2[LUTN];     // {sig(i), sig(i+1)-sig(i)}

// =====================================================================
// low-level helpers
// =====================================================================
__device__ __forceinline__ uint32_t smem_u32(const void* p) {
    uint32_t a;
    asm("{ .reg .u64 t; cvta.to.shared.u64 t, %1; cvt.u32.u64 %0, t; }" : "=r"(a) : "l"(p));
    return a;
}
__device__ __forceinline__ void cp16(uint32_t dst, const void* src) {
    asm volatile("cp.async.cg.shared.global [%0], [%1], 16;" :: "r"(dst), "l"(src));
}
__device__ __forceinline__ void cp_commit() {
    asm volatile("cp.async.commit_group;" ::: "memory");
}
__device__ __forceinline__ void ldsm4(uint32_t addr, uint32_t& r0, uint32_t& r1,
                                      uint32_t& r2, uint32_t& r3) {
    asm volatile("ldmatrix.sync.aligned.m8n8.x4.shared.b16 {%0,%1,%2,%3}, [%4];"
                 : "=r"(r0), "=r"(r1), "=r"(r2), "=r"(r3) : "r"(addr));
}
__device__ __forceinline__ void ldsm4t(uint32_t addr, uint32_t& r0, uint32_t& r1,
                                       uint32_t& r2, uint32_t& r3) {
    asm volatile("ldmatrix.sync.aligned.m8n8.x4.trans.shared.b16 {%0,%1,%2,%3}, [%4];"
                 : "=r"(r0), "=r"(r1), "=r"(r2), "=r"(r3) : "r"(addr));
}
__device__ __forceinline__ void mma16816(float* d, const uint32_t* a, uint32_t b0, uint32_t b1) {
    asm volatile("mma.sync.aligned.m16n8k16.row.col.f32.bf16.bf16.f32 "
                 "{%0,%1,%2,%3}, {%4,%5,%6,%7}, {%8,%9}, {%0,%1,%2,%3};"
                 : "+f"(d[0]), "+f"(d[1]), "+f"(d[2]), "+f"(d[3])
                 : "r"(a[0]), "r"(a[1]), "r"(a[2]), "r"(a[3]), "r"(b0), "r"(b1));
}

// swizzled smem offset: 128B rows, 16B chunks, c8 ^= (r & 7)
#define SWZ(r, c8) ((((uint32_t)(r)) << 7) + ((((uint32_t)(c8)) ^ ((uint32_t)(r) & 7)) << 4))

__device__ __forceinline__ void load_tile128(uint32_t dst, const bf16* __restrict__ src,
                                             int tid) {
#pragma unroll
    for (int i = 0; i < 4; i++) {
        int ch = tid + i * 256;
        int r = ch >> 3, c8 = ch & 7;
        cp16(dst + SWZ(r, c8), src + (size_t)r * 512 + c8 * 8);
    }
}
__device__ __forceinline__ void load_tile64(uint32_t dst, const bf16* __restrict__ src,
                                            int tid) {
#pragma unroll
    for (int i = 0; i < 2; i++) {
        int ch = tid + i * 256;
        int r = ch >> 3, c8 = ch & 7;
        cp16(dst + SWZ(r, c8), src + (size_t)r * 512 + c8 * 8);
    }
}

// warp tile 32(m) x 32(n), B n-major (NT), acc[2][4][4]  -- 128x64 CTA tiles
__device__ __forceinline__ void mma_slab_m32n32_nt(uint32_t As, uint32_t Bs,
                                                   int warp_m0, int warp_n0, int lane,
                                                   float acc[2][4][4]) {
#pragma unroll
    for (int kk = 0; kk < 4; kk++) {
        uint32_t a[2][4];
#pragma unroll
        for (int mi = 0; mi < 2; mi++) {
            int r = warp_m0 + mi * 16 + (lane & 15);
            uint32_t addr = As + (r << 7) + ((((kk << 1) + (lane >> 4)) ^ (r & 7)) << 4);
            ldsm4(addr, a[mi][0], a[mi][1], a[mi][2], a[mi][3]);
        }
#pragma unroll
        for (int pr = 0; pr < 2; pr++) {
            int nr = warp_n0 + pr * 16 + (lane & 7) + ((lane >> 4) << 3);
            uint32_t addr = Bs + (nr << 7) + ((((kk << 1) + ((lane >> 3) & 1)) ^ (nr & 7)) << 4);
            uint32_t b0, b1, b2, b3;
            ldsm4(addr, b0, b1, b2, b3);
#pragma unroll
            for (int mi = 0; mi < 2; mi++) {
                mma16816(acc[mi][2 * pr + 0], a[mi], b0, b1);
                mma16816(acc[mi][2 * pr + 1], a[mi], b2, b3);
            }
        }
    }
}

// warp tile 16(m) x 32(n), B n-major (NT), acc[4][4]
__device__ __forceinline__ void mma_slab_m16n32_nt(uint32_t As, uint32_t Bs,
                                                   int warp_m0, int warp_n0, int lane,
                                                   float acc[4][4]) {
#pragma unroll
    for (int kk = 0; kk < 4; kk++) {
        uint32_t a[4];
        {
            int r = warp_m0 + (lane & 15);
            uint32_t addr = As + (r << 7) + ((((kk << 1) + (lane >> 4)) ^ (r & 7)) << 4);
            ldsm4(addr, a[0], a[1], a[2], a[3]);
        }
#pragma unroll
        for (int pr = 0; pr < 2; pr++) {
            int nr = warp_n0 + pr * 16 + (lane & 7) + ((lane >> 4) << 3);
            uint32_t addr = Bs + (nr << 7) + ((((kk << 1) + ((lane >> 3) & 1)) ^ (nr & 7)) << 4);
            uint32_t b0, b1, b2, b3;
            ldsm4(addr, b0, b1, b2, b3);
            mma16816(acc[2 * pr + 0], a, b0, b1);
            mma16816(acc[2 * pr + 1], a, b2, b3);
        }
    }
}

// warp tile 16(m) x 32(n), B k-major (trans), acc[4][4]
__device__ __forceinline__ void mma_slab_m16n32_t(uint32_t As, uint32_t Bs,
                                                  int warp_m0, int warp_n0, int lane,
                                                  float acc[4][4]) {
#pragma unroll
    for (int kk = 0; kk < 4; kk++) {
        uint32_t a[4];
        {
            int r = warp_m0 + (lane & 15);
            uint32_t addr = As + (r << 7) + ((((kk << 1) + (lane >> 4)) ^ (r & 7)) << 4);
            ldsm4(addr, a[0], a[1], a[2], a[3]);
        }
#pragma unroll
        for (int pr = 0; pr < 2; pr++) {
            int kr = kk * 16 + (lane & 15);
            int c8 = ((warp_n0 + pr * 16) >> 3) + (lane >> 4);
            uint32_t addr = Bs + (kr << 7) + ((c8 ^ (kr & 7)) << 4);
            uint32_t b0, b1, b2, b3;
            ldsm4t(addr, b0, b1, b2, b3);
            mma16816(acc[2 * pr + 0], a, b0, b1);
            mma16816(acc[2 * pr + 1], a, b2, b3);
        }
    }
}

#define STG_MID   24576
#define SMEM_MID  (3 * STG_MID)
#define STG_SM    16384
#define SMEM_SM   (3 * STG_SM)

// =====================================================================
// QKV GEMM, CTA tile 128(m) x 64(n), warp 32x32, 3-stage; split bf16 out
// grid (24, 16) = 384 CTAs
// =====================================================================
__global__ __launch_bounds__(256) void gemm_qkv(
    const bf16* __restrict__ Ahi, const bf16* __restrict__ Alo,
    const bf16* __restrict__ Bhi, const bf16* __restrict__ Blo,
    const float* __restrict__ bias,
    bf16* __restrict__ ohi, bf16* __restrict__ olo)
{
    extern __shared__ char dsm[];
    const uint32_t sb = smem_u32(dsm);
    const int tid = threadIdx.x;
    const int lane = tid & 31, w = tid >> 5;
    const int warp_m0 = (w >> 1) * 32, warp_n0 = (w & 1) * 32;
    const int bn = blockIdx.x * 64, bm = blockIdx.y * 128;
    const int NS = 24;

    float acc[2][4][4];
#pragma unroll
    for (int mi = 0; mi < 2; mi++)
#pragma unroll
        for (int nf = 0; nf < 4; nf++)
#pragma unroll
            for (int q = 0; q < 4; q++) acc[mi][nf][q] = 0.f;

#define LOAD_SLAB(s, st)                                                        \
    do {                                                                        \
        int part = (s) >> 3;                                                    \
        int k0 = ((s) & 7) * 64;                                                \
        const bf16* Asrc = ((part == 2) ? Alo : Ahi) + (size_t)bm * 512 + k0;   \
        const bf16* Bsrc = ((part == 1) ? Blo : Bhi) + (size_t)bn * 512 + k0;   \
        load_tile128(sb + (st) * STG_MID, Asrc, tid);                           \
        load_tile64(sb + (st) * STG_MID + 16384, Bsrc, tid);                    \
        cp_commit();                                                            \
    } while (0)

    LOAD_SLAB(0, 0);
    LOAD_SLAB(1, 1);
#pragma unroll 1
    for (int s = 0; s < NS; s++) {
        if (s + 2 < NS) {
            LOAD_SLAB(s + 2, (s + 2) % 3);
            asm volatile("cp.async.wait_group 2;" ::: "memory");
        } else if (s + 1 < NS) {
            asm volatile("cp.async.wait_group 1;" ::: "memory");
        } else {
            asm volatile("cp.async.wait_group 0;" ::: "memory");
        }
        __syncthreads();
        uint32_t st = sb + (s % 3) * STG_MID;
        mma_slab_m32n32_nt(st, st + 16384, warp_m0, warp_n0, lane, acc);
        __syncthreads();
    }
#undef LOAD_SLAB

    const int mrow = lane >> 2, ncol = 2 * (lane & 3);
#pragma unroll
    for (int mi = 0; mi < 2; mi++) {
#pragma unroll
        for (int nf = 0; nf < 4; nf++) {
            int n_g = bn + warp_n0 + nf * 8 + ncol;
            float2 bb = *(const float2*)(bias + n_g);
#pragma unroll
            for (int hh = 0; hh < 2; hh++) {
                int m = bm + warp_m0 + mi * 16 + mrow + hh * 8;
                float v0 = acc[mi][nf][hh * 2 + 0] + bb.x;
                float v1 = acc[mi][nf][hh * 2 + 1] + bb.y;
                int seg = n_g >> 9, col = n_g & 511;
                bf16 h0 = __float2bfloat16(v0), h1 = __float2bfloat16(v1);
                __nv_bfloat162 hv; hv.x = h0; hv.y = h1;
                __nv_bfloat162 lv;
                lv.x = __float2bfloat16(v0 - __bfloat162float(h0));
                lv.y = __float2bfloat16(v1 - __bfloat162float(h1));
                *(__nv_bfloat162*)(ohi + (size_t)seg * SZQ + (size_t)m * 512 + col) = hv;
                *(__nv_bfloat162*)(olo + (size_t)seg * SZQ + (size_t)m * 512 + col) = lv;
            }
        }
    }
}

// =====================================================================
// O-proj GEMM: CTA tile 64x64, warp 16x32, NS=24, fp32 out + bias
// grid (8, 32) = 256 CTAs
// =====================================================================
__global__ __launch_bounds__(256) void gemm_oproj(
    const float* __restrict__ bias, float* __restrict__ outf)
{
    extern __shared__ char dsm[];
    const uint32_t sb = smem_u32(dsm);
    const int tid = threadIdx.x;
    const int lane = tid & 31, w = tid >> 5;
    const int warp_m0 = (w >> 1) * 16, warp_n0 = (w & 1) * 32;
    const int bn = blockIdx.x * 64, bm = blockIdx.y * 64;
    const int NS = 24;

    float acc[4][4];
#pragma unroll
    for (int nf = 0; nf < 4; nf++)
#pragma unroll
        for (int q = 0; q < 4; q++) acc[nf][q] = 0.f;

#define LOAD_SLAB(s, st)                                                        \
    do {                                                                        \
        int part = (s) >> 3;                                                    \
        int k0 = ((s) & 7) * 64;                                                \
        const bf16* Asrc = ((part == 2) ? g_clo : g_chi) + (size_t)bm * 512 + k0; \
        const bf16* Bsrc = ((part == 1) ? g_wolo : g_wohi) + (size_t)bn * 512 + k0; \
        load_tile64(sb + (st) * STG_SM, Asrc, tid);                             \
        load_tile64(sb + (st) * STG_SM + 8192, Bsrc, tid);                      \
        cp_commit();                                                            \
    } while (0)

    LOAD_SLAB(0, 0);
    LOAD_SLAB(1, 1);
#pragma unroll 1
    for (int s = 0; s < NS; s++) {
        if (s + 2 < NS) {
            LOAD_SLAB(s + 2, (s + 2) % 3);
            asm volatile("cp.async.wait_group 2;" ::: "memory");
        } else if (s + 1 < NS) {
            asm volatile("cp.async.wait_group 1;" ::: "memory");
        } else {
            asm volatile("cp.async.wait_group 0;" ::: "memory");
        }
        __syncthreads();
        uint32_t st = sb + (s % 3) * STG_SM;
        mma_slab_m16n32_nt(st, st + 8192, warp_m0, warp_n0, lane, acc);
        __syncthreads();
    }
#undef LOAD_SLAB

    const int mrow = lane >> 2, ncol = 2 * (lane & 3);
#pragma unroll
    for (int nf = 0; nf < 4; nf++) {
        int n_g = bn + warp_n0 + nf * 8 + ncol;
        float2 bb = *(const float2*)(bias + n_g);
#pragma unroll
        for (int hh = 0; hh < 2; hh++) {
            int m = bm + warp_m0 + mrow + hh * 8;
            float2 o;
            o.x = acc[nf][hh * 2 + 0] + bb.x;
            o.y = acc[nf][hh * 2 + 1] + bb.y;
            *(float2*)(outf + (size_t)m * 512 + n_g) = o;
        }
    }
}

// =====================================================================
// scores: per (b,h) S = Q K^T; CTA tile 64x64, warp 16x32
// grid (8, 8, 32)
// =====================================================================
__global__ __launch_bounds__(256) void gemm_scores_mma()
{
    extern __shared__ char dsm[];
    const uint32_t sb = smem_u32(dsm);
    const int tid = threadIdx.x;
    const int lane = tid & 31, w = tid >> 5;
    const int warp_m0 = (w >> 1) * 16, warp_n0 = (w & 1) * 32;
    int bh = blockIdx.z;
    int b = bh >> 3, h = bh & 7;
    int bn = blockIdx.x * 64, bm = blockIdx.y * 64;
    const int NS = 3;

    float acc[4][4];
#pragma unroll
    for (int nf = 0; nf < 4; nf++)
#pragma unroll
        for (int q = 0; q < 4; q++) acc[nf][q] = 0.f;

#define LOAD_SLAB(s, st)                                                                    \
    do {                                                                                    \
        const bf16* Asrc = ((s) == 2 ? g_qlo : g_qhi) + (size_t)(b * 512 + bm) * 512 + h * 64; \
        const bf16* Bsrc = ((s) == 1 ? g_qlo : g_qhi) + SZQ + (size_t)(b * 512 + bn) * 512 + h * 64; \
        load_tile64(sb + (st) * STG_SM, Asrc, tid);                                         \
        load_tile64(sb + (st) * STG_SM + 8192, Bsrc, tid);                                  \
        cp_commit();                                                                        \
    } while (0)

    LOAD_SLAB(0, 0);
    LOAD_SLAB(1, 1);
#pragma unroll 1
    for (int s = 0; s < NS; s++) {
        if (s + 2 < NS) {
            LOAD_SLAB(s + 2, (s + 2) % 3);
            asm volatile("cp.async.wait_group 2;" ::: "memory");
        } else if (s + 1 < NS) {
            asm volatile("cp.async.wait_group 1;" ::: "memory");
        } else {
            asm volatile("cp.async.wait_group 0;" ::: "memory");
        }
        __syncthreads();
        uint32_t st = sb + (s % 3) * STG_SM;
        mma_slab_m16n32_nt(st, st + 8192, warp_m0, warp_n0, lane, acc);
        __syncthreads();
    }
#undef LOAD_SLAB

    float* Cp = g_scores + (size_t)bh * Ss * Ss;
    const int mrow = lane >> 2, ncol = 2 * (lane & 3);
#pragma unroll
    for (int nf = 0; nf < 4; nf++) {
        int n_g = bn + warp_n0 + nf * 8 + ncol;
#pragma unroll
        for (int hh = 0; hh < 2; hh++) {
            int m = bm + warp_m0 + mrow + hh * 8;
            float2 o;
            o.x = acc[nf][hh * 2 + 0];
            o.y = acc[nf][hh * 2 + 1];
            *(float2*)(Cp + (size_t)m * 512 + n_g) = o;
        }
    }
}

// =====================================================================
// attn*V: per (b,h) ctx = P V; CTA tile 64(m)x64(n), warp 16x32
// =====================================================================
__global__ __launch_bounds__(256) void gemm_attnv_mma()
{
    extern __shared__ char dsm[];
    const uint32_t sb = smem_u32(dsm);
    const int tid = threadIdx.x;
    const int lane = tid & 31, w = tid >> 5;
    const int warp_m0 = (w >> 1) * 16, warp_n0 = (w & 1) * 32;
    int bh = blockIdx.y;
    int b = bh >> 3, h = bh & 7;
    int bm = blockIdx.x * 64;
    const size_t pbase = (size_t)bh * Ss * Ss;
    const int NS = 24;

    float acc[4][4];
#pragma unroll
    for (int nf = 0; nf < 4; nf++)
#pragma unroll
        for (int q = 0; q < 4; q++) acc[nf][q] = 0.f;

#define LOAD_SLAB(s, st)                                                                     \
    do {                                                                                     \
        int part = (s) >> 3;                                                                 \
        int k0 = ((s) & 7) * 64;                                                             \
        const bf16* Asrc = ((part == 2) ? g_plo : g_phi) + pbase + (size_t)bm * 512 + k0;    \
        const bf16* Bsrc = ((part == 1) ? g_qlo : g_qhi) + 2 * (size_t)SZQ                   \
                           + (size_t)(b * 512 + k0) * 512 + h * 64;                          \
        load_tile64(sb + (st) * STG_SM, Asrc, tid);                                          \
        load_tile64(sb + (st) * STG_SM + 8192, Bsrc, tid);                                   \
        cp_commit();                                                                         \
    } while (0)

    LOAD_SLAB(0, 0);
    LOAD_SLAB(1, 1);
#pragma unroll 1
    for (int s = 0; s < NS; s++) {
        if (s + 2 < NS) {
            LOAD_SLAB(s + 2, (s + 2) % 3);
            asm volatile("cp.async.wait_group 2;" ::: "memory");
        } else if (s + 1 < NS) {
            asm volatile("cp.async.wait_group 1;" ::: "memory");
        } else {
            asm volatile("cp.async.wait_group 0;" ::: "memory");
        }
        __syncthreads();
        uint32_t st = sb + (s % 3) * STG_SM;
        mma_slab_m16n32_t(st, st + 8192, warp_m0, warp_n0, lane, acc);
        __syncthreads();
    }
#undef LOAD_SLAB

    const int mrow = lane >> 2, ncol = 2 * (lane & 3);
#pragma unroll
    for (int nf = 0; nf < 4; nf++) {
        int n_g = h * 64 + warp_n0 + nf * 8 + ncol;
#pragma unroll
        for (int hh = 0; hh < 2; hh++) {
            int m = b * 512 + bm + warp_m0 + mrow + hh * 8;
            float v0 = acc[nf][hh * 2 + 0];
            float v1 = acc[nf][hh * 2 + 1];
            bf16 h0 = __float2bfloat16(v0), h1 = __float2bfloat16(v1);
            __nv_bfloat162 hv; hv.x = h0; hv.y = h1;
            __nv_bfloat162 lv;
            lv.x = __float2bfloat16(v0 - __bfloat162float(h0));
            lv.y = __float2bfloat16(v1 - __bfloat162float(h1));
            *(__nv_bfloat162*)(g_chi + (size_t)m * 512 + n_g) = hv;
            *(__nv_bfloat162*)(g_clo + (size_t)m * 512 + n_g) = lv;
        }
    }
}

// =====================================================================
// reductions
// =====================================================================
__device__ __forceinline__ float warp_sum(float v) {
#pragma unroll
    for (int o = 16; o; o >>= 1) v += __shfl_xor_sync(0xffffffffu, v, o);
    return v;
}
template <int NV, int NW>
__device__ __forceinline__ void block_sumN(float* v, float* red) {
    int lane = threadIdx.x & 31, w = threadIdx.x >> 5;
#pragma unroll
    for (int i = 0; i < NV; i++) v[i] = warp_sum(v[i]);
    if (lane == 0)
#pragma unroll
        for (int i = 0; i < NV; i++) red[w * NV + i] = v[i];
    __syncthreads();
    if (w == 0) {
#pragma unroll
        for (int i = 0; i < NV; i++) {
            float x = (lane < NW) ? red[lane * NV + i] : 0.f;
            x = warp_sum(x);
            if (lane == 0) red[i] = x;
        }
    }
    __syncthreads();
#pragma unroll
    for (int i = 0; i < NV; i++) v[i] = red[i];
    __syncthreads();
}

// =====================================================================
// exact sig(mv) evaluator (used only by LUT build)
// =====================================================================
__device__ __forceinline__ float sig_exact(float mv, const float* __restrict__ w1,
                                           const float* __restrict__ b1,
                                           const float* __restrict__ w2, float b2v)
{
    float scaled = mv * 0.05f;
    float av = 0.f;
#pragma unroll 8
    for (int hh = 0; hh < HIDh; hh++) {
        float hv = fmaf(scaled, w1[hh], b1[hh]);
        hv = fminf(fmaxf(hv, 0.f), 5.f);
        av = fmaf(hv, w2[hh], av);
    }
    av += b2v;
    av = fminf(fmaxf(av, -5.f), 5.f);
    float taylor = fminf(fmaxf(fmaf(av, 2.5f, 1.f), 0.5f), 1.5f);
    return 1.f / (1.f + __expf(-taylor));
}

// =====================================================================
// fused conversion kernel, float4 per thread
// =====================================================================
__device__ __forceinline__ void conv4(const float* __restrict__ src, bf16* hi, bf16* lo,
                                      float scale, int i4)
{
    float4 a = *(const float4*)(src + i4 * 4);
    a.x *= scale; a.y *= scale; a.z *= scale; a.w *= scale;
    __nv_bfloat162 h01, h23, l01, l23;
    h01.x = __float2bfloat16(a.x); h01.y = __float2bfloat16(a.y);
    h23.x = __float2bfloat16(a.z); h23.y = __float2bfloat16(a.w);
    l01.x = __float2bfloat16(a.x - __bfloat162float(h01.x));
    l01.y = __float2bfloat16(a.y - __bfloat162float(h01.y));
    l23.x = __float2bfloat16(a.z - __bfloat162float(h23.x));
    l23.y = __float2bfloat16(a.w - __bfloat162float(h23.y));
    *(__nv_bfloat162*)(hi + i4 * 4 + 0) = h01;
    *(__nv_bfloat162*)(hi + i4 * 4 + 2) = h23;
    *(__nv_bfloat162*)(lo + i4 * 4 + 0) = l01;
    *(__nv_bfloat162*)(lo + i4 * 4 + 2) = l23;
}

__global__ __launch_bounds__(256) void conv_all(
    const float* __restrict__ x,
    const float* __restrict__ wq, const float* __restrict__ wk,
    const float* __restrict__ wv, const float* __restrict__ wo,
    const float* __restrict__ bq, const float* __restrict__ bk,
    const float* __restrict__ bv,
    const float* __restrict__ w1, const float* __restrict__ b1,
    const float* __restrict__ w2, const float* __restrict__ b2p)
{
    int bid = blockIdx.x;
    int tid = threadIdx.x;
    if (bid < 1024) {
        conv4(x, g_xhi, g_xlo, 1.f, bid * 256 + tid);
    } else if (bid < 1280) {
        conv4(wq, g_whi, g_wlo, 0.125f, (bid - 1024) * 256 + tid);
    } else if (bid < 1536) {
        conv4(wk, g_whi + Ee * Ee, g_wlo + Ee * Ee, 1.f, (bid - 1280) * 256 + tid);
    } else if (bid < 1792) {
        conv4(wv, g_whi + 2 * Ee * Ee, g_wlo + 2 * Ee * Ee, 1.f, (bid - 1536) * 256 + tid);
    } else if (bid < 2048) {
        conv4(wo, g_wohi, g_wolo, 1.f, (bid - 1792) * 256 + tid);
    } else if (bid < 2055) {
        int j = (bid - 2048) * 256 + tid;
        if (j < 1536) {
            float v = (j < 512) ? bq[j] * 0.125f : (j < 1024 ? bk[j - 512] : bv[j - 1024]);
            g_biasqkv[j] = v;
        }
    } else {
        int j = (bid - 2055) * 256 + tid;
        if (j < LUTN) {
            float b2v = b2p[0];
            float step = 16.f / (float)LUTN;
            float m0 = -8.f + step * (float)j;
            float s0 = sig_exact(m0, w1, b1, w2, b2v);
            float s1 = sig_exact(m0 + step, w1, b1, w2, b2v);
            float2 e; e.x = s0; e.y = s1 - s0;
            g_lut2[j] = e;
        }
    }
}

// =====================================================================
// transform: WARP-PER-ROW (no block barriers). 128 thr = 4 rows/block.
// lane owns 16 cols as 4 x float4 at j4 = (lane + 32k).
// grid Bb*Ss/4 = 512
// =====================================================================
__global__ __launch_bounds__(128) void transform_kernel()
{
    int warp = threadIdx.x >> 5, lane = threadIdx.x & 31;
    int row = blockIdx.x * 4 + warp;
    int b = row >> 9, i = row & (Ss - 1);

    const float* base = g_scores + (((size_t)(b * Hh)) * Ss + i) * Ss;
    float e1[4][4], sig[4][4];
    float s_e1 = 0.f, s_m = 0.f, s_m2 = 0.f;
#pragma unroll
    for (int k = 0; k < 4; k++) {
        int j4 = (lane + 32 * k) * 4;
        float4 acc4 = make_float4(0.f, 0.f, 0.f, 0.f);
#pragma unroll
        for (int h = 0; h < Hh; h++) {
            float4 v = *(const float4*)(base + (size_t)h * Ss * Ss + j4);
            acc4.x += fminf(fmaxf(v.x, -15.f), 15.f);
            acc4.y += fminf(fmaxf(v.y, -15.f), 15.f);
            acc4.z += fminf(fmaxf(v.z, -15.f), 15.f);
            acc4.w += fminf(fmaxf(v.w, -15.f), 15.f);
        }
        float mv[4] = {acc4.x * 0.125f, acc4.y * 0.125f, acc4.z * 0.125f, acc4.w * 0.125f};
#pragma unroll
        for (int q = 0; q < 4; q++) {
            float m = mv[q];
            float mc8 = fminf(fmaxf(m, -8.f), 8.f);
            float f = (mc8 + 8.f) * ((float)LUTN / 16.f);
            int idx = min((int)f, LUTN - 1);
            float frac = f - (float)idx;
            float2 e = __ldg(&g_lut2[idx]);
            sig[k][q] = fmaf(frac, e.y, e.x);
            float mc = fminf(fmaxf(m, -10.f), 10.f);
            e1[k][q] = __expf(mc - 10.f);
            s_e1 += e1[k][q];
            s_m += m;
            s_m2 += m * m;
        }
    }
    float S1 = warp_sum(s_e1);
    s_m  = warp_sum(s_m);
    s_m2 = warp_sum(s_m2);

    float s_e2 = 0.f;
    float e2[4][4];
#pragma unroll
    for (int k = 0; k < 4; k++)
#pragma unroll
        for (int q = 0; q < 4; q++) {
            float p = e1[k][q] / S1;
            float Hent = -p * __logf(p + 1e-6f);
            e2[k][q] = __expf(fmaf(3.f, Hent, -1.2f));   // 3*Hent <= 3/e < 1.2
            s_e2 += e2[k][q];
        }
    float S2 = warp_sum(s_e2);

    float s_t = 0.f, s_t2 = 0.f;
    float* trow = g_tpre + (size_t)row * Ss;
#pragma unroll
    for (int k = 0; k < 4; k++) {
        float4 tv;
        float t0 = sig[k][0] * (e2[k][0] / S2);
        float t1 = sig[k][1] * (e2[k][1] / S2);
        float t2 = sig[k][2] * (e2[k][2] / S2);
        float t3 = sig[k][3] * (e2[k][3] / S2);
        tv.x = t0; tv.y = t1; tv.z = t2; tv.w = t3;
        *(float4*)(trow + (lane + 32 * k) * 4) = tv;
        s_t  += t0 + t1 + t2 + t3;
        s_t2 += t0 * t0 + t1 * t1 + t2 * t2 + t3 * t3;
    }
    s_t  = warp_sum(s_t);
    s_t2 = warp_sum(s_t2);
    if (lane == 0) {
        g_partial[row * 4 + 0] = s_m;
        g_partial[row * 4 + 1] = s_m2;
        g_partial[row * 4 + 2] = s_t;
        g_partial[row * 4 + 3] = s_t2;
    }
}

__global__ __launch_bounds__(512) void scalars_kernel()
{
    __shared__ float red[64];
    int b = blockIdx.x;
    int t = threadIdx.x;
    const float* pr = g_partial + (size_t)(b * Ss + t) * 4;
    float r4[4] = {pr[0], pr[1], pr[2], pr[3]};
    block_sumN<4, 16>(r4, red);
    if (t == 0) {
        const float N = (float)(Ss * Ss);
        float s0 = r4[0], s1 = r4[1], s2 = r4[2], s3 = r4[3];
        float e_o = sqrtf(s1) + 1e-4f;
        float e_t = sqrtf(s3) + 1e-4f;
        float gamma = fminf(fmaxf(e_o / e_t, 0.8f), 1.2f);
        float mu_t = s2 / N, mu_o = s0 / N;
        float var_t = gamma * gamma * (s3 / N - mu_t * mu_t);
        float t_std = sqrtf(fmaxf(var_t, 0.01f));
        float var_o = s1 / N - mu_o * mu_o;
        float o_std = sqrtf(fmaxf(var_o, 0.01f));
        float gdyn = fminf(fmaxf(o_std / t_std, 0.8f), 1.2f);
        float A = gdyn * gamma;
        g_Acoef[b] = A;
        g_Ccoef[b] = mu_o - A * mu_t;
    }
}

// =====================================================================
// blend + softmax: WARP-PER-ROW, no barriers. 128 thr = 4 rows/block.
// grid Bb*Hh*Ss/4 = 4096
// =====================================================================
__global__ __launch_bounds__(128) void softmax_kernel()
{
    int warp = threadIdx.x >> 5, lane = threadIdx.x & 31;
    int rowid = blockIdx.x * 4 + warp;
    int b = rowid >> 12;
    int i = rowid & (Ss - 1);
    const float* srow = g_scores + (size_t)rowid * Ss;
    const float* trow = g_tpre + (((size_t)(b * Ss)) + i) * Ss;
    float A = g_Acoef[b], C = g_Ccoef[b];

    float e[4][4];
    float ls = 0.f;
#pragma unroll
    for (int k = 0; k < 4; k++) {
        int j4 = (lane + 32 * k) * 4;
        float4 sv = *(const float4*)(srow + j4);
        float4 tv = *(const float4*)(trow + j4);
        float sc[4] = {sv.x, sv.y, sv.z, sv.w};
        float tt[4] = {tv.x, tv.y, tv.z, tv.w};
#pragma unroll
        for (int q = 0; q < 4; q++) {
            float s = fminf(fmaxf(sc[q], -15.f), 15.f);
            float t = fmaf(A, tt[q], C);
            s = fminf(fmaxf(fmaf(0.1f, t, s), -15.f), 15.f);
            e[k][q] = __expf(s - 15.f);
            ls += e[k][q];
        }
    }
    float inv = 1.f / warp_sum(ls);

    bf16* ph = g_phi + (size_t)rowid * Ss;
    bf16* pl = g_plo + (size_t)rowid * Ss;
#pragma unroll
    for (int k = 0; k < 4; k++) {
        int j4 = (lane + 32 * k) * 4;
        float p0 = e[k][0] * inv, p1 = e[k][1] * inv;
        float p2 = e[k][2] * inv, p3 = e[k][3] * inv;
        __nv_bfloat162 h01, h23, l01, l23;
        h01.x = __float2bfloat16(p0); h01.y = __float2bfloat16(p1);
        h23.x = __float2bfloat16(p2); h23.y = __float2bfloat16(p3);
        l01.x = __float2bfloat16(p0 - __bfloat162float(h01.x));
        l01.y = __float2bfloat16(p1 - __bfloat162float(h01.y));
        l23.x = __float2bfloat16(p2 - __bfloat162float(h23.x));
        l23.y = __float2bfloat16(p3 - __bfloat162float(h23.y));
        *(__nv_bfloat162*)(ph + j4 + 0) = h01;
        *(__nv_bfloat162*)(ph + j4 + 2) = h23;
        *(__nv_bfloat162*)(pl + j4 + 0) = l01;
        *(__nv_bfloat162*)(pl + j4 + 2) = l23;
    }
}

// ---------------- launch ----------------
extern "C" void kernel_launch(void* const* d_in, const int* in_sizes, int n_in,
                              void* d_out, int out_size)
{
    const float* x  = (const float*)d_in[0];
    const float* wq = (const float*)d_in[1];
    const float* bq = (const float*)d_in[2];
    const float* wk = (const float*)d_in[3];
    const float* bk = (const float*)d_in[4];
    const float* wv = (const float*)d_in[5];
    const float* bv = (const float*)d_in[6];
    const float* wo = (const float*)d_in[7];
    const float* bo = (const float*)d_in[8];
    const float* w1 = (const float*)d_in[9];
    const float* b1 = (const float*)d_in[10];
    const float* w2 = (const float*)d_in[11];
    const float* b2 = (const float*)d_in[12];
    float* out = (float*)d_out;

    void *pxhi, *pxlo, *pwhi, *pwlo, *pbias, *pqhi, *pqlo;
    cudaGetSymbolAddress(&pxhi, g_xhi);   cudaGetSymbolAddress(&pxlo, g_xlo);
    cudaGetSymbolAddress(&pwhi, g_whi);   cudaGetSymbolAddress(&pwlo, g_wlo);
    cudaGetSymbolAddress(&pbias, g_biasqkv);
    cudaGetSymbolAddress(&pqhi, g_qhi);   cudaGetSymbolAddress(&pqlo, g_qlo);

    cudaFuncSetAttribute(gemm_qkv, cudaFuncAttributeMaxDynamicSharedMemorySize, SMEM_MID);
    cudaFuncSetAttribute(gemm_oproj, cudaFuncAttributeMaxDynamicSharedMemorySize, SMEM_SM);
    cudaFuncSetAttribute(gemm_scores_mma, cudaFuncAttributeMaxDynamicSharedMemorySize, SMEM_SM);
    cudaFuncSetAttribute(gemm_attnv_mma, cudaFuncAttributeMaxDynamicSharedMemorySize, SMEM_SM);

    // conversions + bias + LUT in one launch (float4 per thread)
    conv_all<<<2063, 256>>>(x, wq, wk, wv, wo, bq, bk, bv, w1, b1, w2, b2);

    // fused QKV projection (N = 1536), 128x64 tiles -> 384 CTAs
    gemm_qkv<<<dim3(24, 16), 256, SMEM_MID>>>(
        (const bf16*)pxhi, (const bf16*)pxlo, (const bf16*)pwhi, (const bf16*)pwlo,
        (const float*)pbias, (bf16*)pqhi, (bf16*)pqlo);

    gemm_scores_mma<<<dim3(8, 8, Bb * Hh), 256, SMEM_SM>>>();
    transform_kernel<<<Bb * Ss / 4, 128>>>();
    scalars_kernel<<<Bb, 512>>>();
    softmax_kernel<<<Bb * Hh * Ss / 4, 128>>>();
    gemm_attnv_mma<<<dim3(8, Bb * Hh), 256, SMEM_SM>>>();

    // output projection, 64x64 tiles -> 256 CTAs
    gemm_oproj<<<dim3(8, 32), 256, SMEM_SM>>>(bo, out);
}